// round 10
// baseline (speedup 1.0000x reference)
#include <cuda_runtime.h>
#include <cuda_fp16.h>
#include <mma.h>
#include <math.h>
#include <stdint.h>

using namespace nvcuda;

// ---------------------------------------------------------------------------
// Problem constants
// ---------------------------------------------------------------------------
#define BB 32
#define NN 1024
#define DD 768
#define E_TOKN 4
#define E_CHN 4
#define EE 8
#define TOPK 2
#define HNN 4096
#define HDD 3072
#define NPAIR (BB * TOPK)            // 64 selected (batch, expert) pairs
#define HID_ELEMS (DD * HNN)         // 3145728 == NN*HDD
#define CON_ELEMS (NN * DD)          // 786432

// ---------------------------------------------------------------------------
// Static device scratch (uint4-typed: guaranteed 16B alignment).
// RULE (rounds 3-5 root cause): device-global addresses are formed ONLY in
// device code — host-side g_* is the shadow symbol (ATS makes it writable!).
// ---------------------------------------------------------------------------
__device__ float g_xm[BB * DD];
__device__ int   g_pair_e[NPAIR];
__device__ float g_pair_w[NPAIR];

__device__ uint4 g_xf_raw  [BB * NN * DD / 8];          // x fp16 [b][n][d]
__device__ uint4 g_xtf_raw [BB * DD * NN / 8];          // x^T fp16 [b][d][n]
__device__ uint4 g_tw1f_raw[E_TOKN * HNN * NN / 8];
__device__ uint4 g_tw2f_raw[E_TOKN * NN * HNN / 8];
__device__ uint4 g_cw1f_raw[E_CHN * HDD * DD / 8];
__device__ uint4 g_cw2f_raw[E_CHN * DD * HDD / 8];
__device__ uint4 g_hidf_raw[(size_t)NPAIR * HID_ELEMS / 8];   // ~402 MB fp16
__device__ float4 g_contrib_raw[(size_t)NPAIR * CON_ELEMS / 4]; // ~201 MB

#define g_xf   ((__half*)g_xf_raw)
#define g_xtf  ((__half*)g_xtf_raw)
#define g_tw1f ((__half*)g_tw1f_raw)
#define g_tw2f ((__half*)g_tw2f_raw)
#define g_cw1f ((__half*)g_cw1f_raw)
#define g_cw2f ((__half*)g_cw2f_raw)
#define g_hidf ((__half*)g_hidf_raw)
#define g_contrib ((float*)g_contrib_raw)

// ---------------------------------------------------------------------------
// Helpers
// ---------------------------------------------------------------------------
__device__ __forceinline__ float gelu_tanh(float v) {
    const float c = 0.7978845608028654f; // sqrt(2/pi)
    float u = c * (v + 0.044715f * v * v * v);
    return 0.5f * v * (1.0f + tanhf(u));
}

__device__ __forceinline__ uint32_t smem_u32(const void* p) {
    uint32_t a;
    asm("{ .reg .u64 t; cvta.to.shared.u64 t, %1; cvt.u32.u64 %0, t; }"
        : "=r"(a) : "l"(p));
    return a;
}

#define CP_ASYNC16(dst32, src) \
    asm volatile("cp.async.cg.shared.global [%0], [%1], 16;" \
                 :: "r"(dst32), "l"(src) : "memory")
#define CP_COMMIT()  asm volatile("cp.async.commit_group;" ::: "memory")
#define CP_WAIT0()   asm volatile("cp.async.wait_group 0;" ::: "memory")
#define CP_WAIT1()   asm volatile("cp.async.wait_group 1;" ::: "memory")

// ---------------------------------------------------------------------------
// Kernel: xm[b,d] = mean_n x[b,n,d]
// ---------------------------------------------------------------------------
__global__ void k_mean(const float* __restrict__ x) {
    int idx = blockIdx.x * blockDim.x + threadIdx.x;
    if (idx >= BB * DD) return;
    int b = idx / DD;
    int d = idx - b * DD;
    const float* p = x + (size_t)b * NN * DD + d;
    float s = 0.0f;
    #pragma unroll 8
    for (int n = 0; n < NN; n++) s += p[(size_t)n * DD];
    g_xm[idx] = s * (1.0f / (float)NN);
}

// ---------------------------------------------------------------------------
// Kernel: router logits, softmax, top-2, aux loss. Single block, 256 thr.
// ---------------------------------------------------------------------------
__global__ void k_router(const float* __restrict__ rw, float* __restrict__ out,
                         long long aux_idx, int has_aux) {
    __shared__ float probs[BB][EE];
    __shared__ int   top1s[BB];
    __shared__ float partial[EE];
    int t = threadIdx.x;

    {
        int b = t >> 3, e = t & 7;
        const float* xm = g_xm + b * DD;
        const float* w  = rw + e * DD;
        float s = 0.0f;
        #pragma unroll 8
        for (int d = 0; d < DD; d++) s += xm[d] * w[d];
        probs[b][e] = s;
    }
    __syncthreads();

    if (t < BB) {
        float l[EE];
        float mx = -1e30f;
        #pragma unroll
        for (int e = 0; e < EE; e++) { l[e] = probs[t][e]; mx = fmaxf(mx, l[e]); }
        float sum = 0.0f;
        #pragma unroll
        for (int e = 0; e < EE; e++) { l[e] = expf(l[e] - mx); sum += l[e]; }
        float inv = 1.0f / sum;
        #pragma unroll
        for (int e = 0; e < EE; e++) { l[e] *= inv; probs[t][e] = l[e]; }
        int i0 = 0; float v0 = l[0];
        #pragma unroll
        for (int e = 1; e < EE; e++) if (l[e] > v0) { v0 = l[e]; i0 = e; }
        int i1 = -1; float v1 = -1e30f;
        #pragma unroll
        for (int e = 0; e < EE; e++) if (e != i0 && l[e] > v1) { v1 = l[e]; i1 = e; }
        float inv01 = 1.0f / (v0 + v1);
        g_pair_e[2 * t]     = i0; g_pair_w[2 * t]     = v0 * inv01;
        g_pair_e[2 * t + 1] = i1; g_pair_w[2 * t + 1] = v1 * inv01;
        top1s[t] = i0;
    }
    __syncthreads();

    if (t < EE) {
        float ps = 0.0f; int c = 0;
        for (int b = 0; b < BB; b++) { ps += probs[b][t]; c += (top1s[b] == t); }
        partial[t] = ps * (float)c;
    }
    __syncthreads();

    if (t == 0 && has_aux) {
        float s = 0.0f;
        #pragma unroll
        for (int e = 0; e < EE; e++) s += partial[e];
        out[aux_idx] = s * ((float)EE / ((float)BB * (float)BB));
    }
}

// ---------------------------------------------------------------------------
// Fused conversion kernel: all fp32 -> fp16 conversions + x transpose.
// ---------------------------------------------------------------------------
#define NB_X   24576
#define NB_XT  24576
#define NB_TW1 16384
#define NB_TW2 16384
#define NB_CW1 9216
#define NB_CW2 9216
#define NB_TOTAL (NB_X + NB_XT + NB_TW1 + NB_TW2 + NB_CW1 + NB_CW2)

__device__ __forceinline__ void cvt4(const float* __restrict__ s, __half* d, int i) {
    float4 v = ((const float4*)s)[i];
    __half2 a = __floats2half2_rn(v.x, v.y);
    __half2 b = __floats2half2_rn(v.z, v.w);
    uint2 u;
    u.x = *reinterpret_cast<uint32_t*>(&a);
    u.y = *reinterpret_cast<uint32_t*>(&b);
    ((uint2*)d)[i] = u;
}

__global__ void k_convert(const float* __restrict__ x,
                          const float* __restrict__ tw1,
                          const float* __restrict__ tw2,
                          const float* __restrict__ cw1,
                          const float* __restrict__ cw2) {
    __shared__ float t[32][33];
    int bid = blockIdx.x;
    int tid = threadIdx.x;

    if (bid < NB_X) {
        cvt4(x, g_xf, bid * 256 + tid);
    } else if (bid < NB_X + NB_XT) {
        int r = bid - NB_X;
        int b = r / 768;
        int rem = r - b * 768;
        int nblk = rem / 24;
        int dblk = rem - nblk * 24;
        int d0 = dblk * 32, n0 = nblk * 32;
        int tx = tid & 31, ty = tid >> 5;
        #pragma unroll
        for (int i = 0; i < 4; i++) {
            int n = n0 + ty + i * 8;
            t[ty + i * 8][tx] = x[((size_t)b * NN + n) * DD + d0 + tx];
        }
        __syncthreads();
        #pragma unroll
        for (int i = 0; i < 4; i++) {
            int d = d0 + ty + i * 8;
            g_xtf[((size_t)b * DD + d) * NN + n0 + tx] =
                __float2half_rn(t[tx][ty + i * 8]);
        }
    } else if (bid < NB_X + NB_XT + NB_TW1) {
        cvt4(tw1, g_tw1f, (bid - NB_X - NB_XT) * 256 + tid);
    } else if (bid < NB_X + NB_XT + NB_TW1 + NB_TW2) {
        cvt4(tw2, g_tw2f, (bid - NB_X - NB_XT - NB_TW1) * 256 + tid);
    } else if (bid < NB_X + NB_XT + NB_TW1 + NB_TW2 + NB_CW1) {
        cvt4(cw1, g_cw1f, (bid - NB_X - NB_XT - NB_TW1 - NB_TW2) * 256 + tid);
    } else {
        cvt4(cw2, g_cw2f, (bid - NB_X - NB_XT - NB_TW1 - NB_TW2 - NB_CW1) * 256 + tid);
    }
}

// ---------------------------------------------------------------------------
// WMMA fp16 GEMM core v3: CTA 128x128, 256 threads = 8 warps (4m x 2n),
// warp tile 32x64, BK=64, cp.async 2-stage. Acc = 8 frags (64 regs) ->
// ~115 regs/thread -> 2 CTAs/SM = 16 warps (vs 12 before).
// mT/nT passed in (merged kernels decode their own block mapping).
// BIAS: 1=per-col(n), 2=per-row(m). TOHALF: write fp16, else fp32.
// ---------------------------------------------------------------------------
#define BK 64
#define RSTR 144                      // bytes per smem row
#define STRDH 72                      // halves per smem row
#define A_TILE_B (128 * RSTR)         // 18432
#define STAGE_B (2 * A_TILE_B)        // 36864
#define SMEM_TOT (2 * STAGE_B)        // 73728

template<int Nn, int K, bool GELU, int BIAS, bool TOHALF>
__device__ __forceinline__ void wmma_core(
        int mT, int nT,
        const __half* A, const __half* B,
        const float* __restrict__ bias,
        float* Cf, __half* Ch) {
    extern __shared__ __align__(128) unsigned char dsm[];
    const uint32_t sbase = smem_u32(dsm);

    const int tid = threadIdx.x, lane = tid & 31, wid = tid >> 5;
    const int wm = wid & 3, wn = wid >> 2;    // 4 x 2 warp grid, 32x64 tiles

    wmma::fragment<wmma::accumulator, 16, 16, 16, float> acc[2][4];
    #pragma unroll
    for (int mt = 0; mt < 2; mt++)
        #pragma unroll
        for (int p = 0; p < 4; p++) wmma::fill_fragment(acc[mt][p], 0.0f);

    const __half* pA = A + (size_t)mT * K;
    const __half* pB = B + (size_t)nT * K;

    // Per stage: A 128 rows + B 128 rows, 8x16B chunks/row = 2048 chunks,
    // 8 per thread.
    auto load_stage = [&](int stage, int chk) {
        uint32_t sb = sbase + stage * STAGE_B;
        #pragma unroll
        for (int it = 0; it < 4; it++) {           // A
            int idx = it * 256 + tid;
            int row = idx >> 3, c = idx & 7;
            CP_ASYNC16(sb + row * RSTR + c * 16,
                       pA + (size_t)row * K + chk * BK + c * 8);
        }
        #pragma unroll
        for (int it = 0; it < 4; it++) {           // B
            int idx = it * 256 + tid;
            int row = idx >> 3, c = idx & 7;
            CP_ASYNC16(sb + A_TILE_B + row * RSTR + c * 16,
                       pB + (size_t)row * K + chk * BK + c * 8);
        }
        CP_COMMIT();
    };

    const int NCH = K / BK;
    load_stage(0, 0);

    for (int chk = 0; chk < NCH; chk++) {
        if (chk + 1 < NCH) {
            load_stage((chk + 1) & 1, chk + 1);
            CP_WAIT1();
        } else {
            CP_WAIT0();
        }
        __syncthreads();

        __half* sA = (__half*)(dsm + (chk & 1) * STAGE_B);
        __half* sB = (__half*)(dsm + (chk & 1) * STAGE_B + A_TILE_B);

        #pragma unroll
        for (int ks = 0; ks < BK / 16; ks++) {
            wmma::fragment<wmma::matrix_a, 16, 16, 16, __half, wmma::row_major> af[2];
            wmma::fragment<wmma::matrix_b, 16, 16, 16, __half, wmma::col_major> bf[4];
            #pragma unroll
            for (int mt = 0; mt < 2; mt++)
                wmma::load_matrix_sync(af[mt], &sA[(wm * 32 + mt * 16) * STRDH + ks * 16], STRDH);
            #pragma unroll
            for (int p = 0; p < 4; p++)
                wmma::load_matrix_sync(bf[p], &sB[(wn * 64 + p * 16) * STRDH + ks * 16], STRDH);
            #pragma unroll
            for (int mt = 0; mt < 2; mt++)
                #pragma unroll
                for (int p = 0; p < 4; p++)
                    wmma::mma_sync(acc[mt][p], af[mt], bf[p], acc[mt][p]);
        }
        __syncthreads();
    }

    // --- epilogue via per-warp 16x16 fp32 staging (smem reuse) ---
    float* st = (float*)dsm + wid * 288;
    const int r  = lane >> 1;        // 0..15
    const int c0 = (lane & 1) * 8;   // 0 or 8
    #pragma unroll
    for (int mt = 0; mt < 2; mt++) {
        #pragma unroll
        for (int p = 0; p < 4; p++) {
            wmma::store_matrix_sync(st, acc[mt][p], 16, wmma::mem_row_major);
            __syncwarp();
            int row = mT + wm * 32 + mt * 16 + r;
            int col = nT + wn * 64 + p * 16 + c0;
            float v[8];
            #pragma unroll
            for (int j = 0; j < 8; j++) v[j] = st[r * 16 + c0 + j];
            if (BIAS == 1) {
                #pragma unroll
                for (int j = 0; j < 8; j++) v[j] += __ldg(&bias[col + j]);
            } else if (BIAS == 2) {
                float rb = __ldg(&bias[row]);
                #pragma unroll
                for (int j = 0; j < 8; j++) v[j] += rb;
            }
            if (GELU) {
                #pragma unroll
                for (int j = 0; j < 8; j++) v[j] = gelu_tanh(v[j]);
            }
            if (TOHALF) {
                __half2 hv[4];
                #pragma unroll
                for (int j = 0; j < 4; j++)
                    hv[j] = __floats2half2_rn(v[2 * j], v[2 * j + 1]);
                *(uint4*)(Ch + (size_t)row * Nn + col) = *(uint4*)hv;
            } else {
                *(float4*)(Cf + (size_t)row * Nn + col)     = *(float4*)&v[0];
                *(float4*)(Cf + (size_t)row * Nn + col + 4) = *(float4*)&v[4];
            }
            __syncwarp();
        }
    }
}

// ---------------------------------------------------------------------------
// Merged L1 kernel: token + channel first layers in one launch.
// grid (192, 1, NPAIR): token pairs use 6(m) x 32(n) tiling; channel 8 x 24.
// ---------------------------------------------------------------------------
__global__ void __launch_bounds__(256, 2)
k_l1(const float* __restrict__ tb1, const float* __restrict__ cb1) {
    int p = blockIdx.z;
    int e = g_pair_e[p];
    int b = p >> 1;
    int bx = blockIdx.x;
    if (e < E_TOKN) {
        // H[p][d][h] = gelu( sum_n xT[b][d][n] * tw1[e][h][n] + b1[e][h] )
        int mt = bx % 6, nt = bx / 6;          // M=DD(6), N=HNN(32)
        wmma_core<HNN, NN, true, 1, true>(
            mt * 128, nt * 128,
            g_xtf + (size_t)b * DD * NN,
            g_tw1f + (size_t)e * HNN * NN,
            tb1 + e * HNN,
            nullptr, g_hidf + (size_t)p * HID_ELEMS);
    } else {
        int ec = e - E_TOKN;
        // G[p][n][h] = gelu( sum_d x[b][n][d] * cw1[e][h][d] + b1[e][h] )
        int mt = bx % 8, nt = bx / 8;          // M=NN(8), N=HDD(24)
        wmma_core<HDD, DD, true, 1, true>(
            mt * 128, nt * 128,
            g_xf + (size_t)b * NN * DD,
            g_cw1f + (size_t)ec * HDD * DD,
            cb1 + ec * HDD,
            nullptr, g_hidf + (size_t)p * HID_ELEMS);
    }
}

// ---------------------------------------------------------------------------
// Merged L2 kernel: token + channel second layers. grid (48, 1, NPAIR);
// both variants tile M=NN(8) x N=DD(6).
// ---------------------------------------------------------------------------
__global__ void __launch_bounds__(256, 2)
k_l2(const float* __restrict__ tb2, const float* __restrict__ cb2) {
    int p = blockIdx.z;
    int e = g_pair_e[p];
    int bx = blockIdx.x;
    int mt = bx % 8, nt = bx / 8;
    if (e < E_TOKN) {
        // contrib[p][n][d] = sum_h tw2[e][n][h] * H[p][d][h] + b2[e][n]
        wmma_core<DD, HNN, false, 2, false>(
            mt * 128, nt * 128,
            g_tw2f + (size_t)e * NN * HNN,
            g_hidf + (size_t)p * HID_ELEMS,
            tb2 + e * NN,
            g_contrib + (size_t)p * CON_ELEMS, nullptr);
    } else {
        int ec = e - E_TOKN;
        // contrib[p][n][d] = sum_h G[p][n][h] * cw2[e][d][h] + b2[e][d]
        wmma_core<DD, HDD, false, 1, false>(
            mt * 128, nt * 128,
            g_hidf + (size_t)p * HID_ELEMS,
            g_cw2f + (size_t)ec * DD * HDD,
            cb2 + ec * DD,
            g_contrib + (size_t)p * CON_ELEMS, nullptr);
    }
}

// ---------------------------------------------------------------------------
// Final combine
// ---------------------------------------------------------------------------
__global__ void k_combine(float* __restrict__ out) {
    long long idx = (long long)blockIdx.x * 256 + threadIdx.x;
    if (idx >= (long long)BB * NN * DD) return;
    int b = (int)(idx / (NN * DD));
    int r = (int)(idx - (long long)b * (NN * DD));
    float v0 = g_pair_w[2 * b]     * g_contrib[(size_t)(2 * b) * CON_ELEMS + r];
    float v1 = g_pair_w[2 * b + 1] * g_contrib[(size_t)(2 * b + 1) * CON_ELEMS + r];
    out[idx] = v0 + v1;
}

// ---------------------------------------------------------------------------
// Launch — only harness pointers cross host->device. ncu capture lands on
// launch index 3 = k_l1 (merged L1 GEMM).
// ---------------------------------------------------------------------------
extern "C" void kernel_launch(void* const* d_in, const int* in_sizes, int n_in,
                              void* d_out, int out_size) {
    const float* x        = (const float*)d_in[0];
    const float* router_w = (const float*)d_in[1];
    const float* tok_w1   = (const float*)d_in[2];
    const float* tok_b1   = (const float*)d_in[3];
    const float* tok_w2   = (const float*)d_in[4];
    const float* tok_b2   = (const float*)d_in[5];
    const float* ch_w1    = (const float*)d_in[6];
    const float* ch_b1    = (const float*)d_in[7];
    const float* ch_w2    = (const float*)d_in[8];
    const float* ch_b2    = (const float*)d_in[9];
    float* out = (float*)d_out;

    long long bnd = (long long)BB * NN * DD;
    int has_aux = (long long)out_size > bnd;

    cudaFuncSetAttribute(k_l1, cudaFuncAttributeMaxDynamicSharedMemorySize, SMEM_TOT);
    cudaFuncSetAttribute(k_l2, cudaFuncAttributeMaxDynamicSharedMemorySize, SMEM_TOT);

    // 0: mean, 1: router, 2: fused conversions
    k_mean<<<(BB * DD + 255) / 256, 256>>>(x);
    k_router<<<1, 256>>>(router_w, out, bnd, has_aux);
    k_convert<<<NB_TOTAL, 256>>>(x, tok_w1, tok_w2, ch_w1, ch_w2);

    // 3: merged L1 GEMM (token 6x32 tiles, channel 8x24 tiles -> both 192)
    dim3 g_l1(192, 1, NPAIR);
    k_l1<<<g_l1, 256, SMEM_TOT>>>(tok_b1, ch_b1);

    // 4: merged L2 GEMM (both 8x6 = 48 tiles)
    dim3 g_l2g(48, 1, NPAIR);
    k_l2<<<g_l2g, 256, SMEM_TOT>>>(tok_b2, ch_b2);

    // 5: combine
    k_combine<<<(unsigned)((bnd + 255) / 256), 256>>>(out);
}

// round 11
// speedup vs baseline: 1.0576x; 1.0576x over previous
#include <cuda_runtime.h>
#include <cuda_fp16.h>
#include <mma.h>
#include <math.h>
#include <stdint.h>

using namespace nvcuda;

// ---------------------------------------------------------------------------
// Problem constants
// ---------------------------------------------------------------------------
#define BB 32
#define NN 1024
#define DD 768
#define E_TOKN 4
#define E_CHN 4
#define EE 8
#define TOPK 2
#define HNN 4096
#define HDD 3072
#define NPAIR (BB * TOPK)            // 64 selected (batch, expert) pairs
#define HID_ELEMS (DD * HNN)         // 3145728 == NN*HDD
#define CON_ELEMS (NN * DD)          // 786432

// ---------------------------------------------------------------------------
// Static device scratch (uint4-typed: guaranteed 16B alignment).
// RULE (rounds 3-5 root cause): device-global addresses are formed ONLY in
// device code — host-side g_* is the shadow symbol (ATS makes it writable!).
// ---------------------------------------------------------------------------
__device__ float g_xm[BB * DD];
__device__ int   g_pair_e[NPAIR];
__device__ float g_pair_w[NPAIR];

__device__ uint4 g_xf_raw  [BB * NN * DD / 8];          // x fp16 [b][n][d]
__device__ uint4 g_xtf_raw [BB * DD * NN / 8];          // x^T fp16 [b][d][n]
__device__ uint4 g_tw1f_raw[E_TOKN * HNN * NN / 8];
__device__ uint4 g_tw2f_raw[E_TOKN * NN * HNN / 8];
__device__ uint4 g_cw1f_raw[E_CHN * HDD * DD / 8];
__device__ uint4 g_cw2f_raw[E_CHN * DD * HDD / 8];
__device__ uint4 g_hidf_raw[(size_t)NPAIR * HID_ELEMS / 8];   // ~402 MB fp16
__device__ float4 g_contrib_raw[(size_t)NPAIR * CON_ELEMS / 4]; // ~201 MB

#define g_xf   ((__half*)g_xf_raw)
#define g_xtf  ((__half*)g_xtf_raw)
#define g_tw1f ((__half*)g_tw1f_raw)
#define g_tw2f ((__half*)g_tw2f_raw)
#define g_cw1f ((__half*)g_cw1f_raw)
#define g_cw2f ((__half*)g_cw2f_raw)
#define g_hidf ((__half*)g_hidf_raw)
#define g_contrib ((float*)g_contrib_raw)

// ---------------------------------------------------------------------------
// Helpers
// ---------------------------------------------------------------------------
__device__ __forceinline__ float gelu_tanh(float v) {
    const float c = 0.7978845608028654f; // sqrt(2/pi)
    float u = c * (v + 0.044715f * v * v * v);
    return 0.5f * v * (1.0f + tanhf(u));
}

__device__ __forceinline__ uint32_t smem_u32(const void* p) {
    uint32_t a;
    asm("{ .reg .u64 t; cvta.to.shared.u64 t, %1; cvt.u32.u64 %0, t; }"
        : "=r"(a) : "l"(p));
    return a;
}

#define CP_ASYNC16(dst32, src) \
    asm volatile("cp.async.cg.shared.global [%0], [%1], 16;" \
                 :: "r"(dst32), "l"(src) : "memory")
#define CP_COMMIT()  asm volatile("cp.async.commit_group;" ::: "memory")
#define CP_WAIT0()   asm volatile("cp.async.wait_group 0;" ::: "memory")
#define CP_WAIT1()   asm volatile("cp.async.wait_group 1;" ::: "memory")

// ---------------------------------------------------------------------------
// Kernel: xm[b,d] = mean_n x[b,n,d]
// ---------------------------------------------------------------------------
__global__ void k_mean(const float* __restrict__ x) {
    int idx = blockIdx.x * blockDim.x + threadIdx.x;
    if (idx >= BB * DD) return;
    int b = idx / DD;
    int d = idx - b * DD;
    const float* p = x + (size_t)b * NN * DD + d;
    float s = 0.0f;
    #pragma unroll 8
    for (int n = 0; n < NN; n++) s += p[(size_t)n * DD];
    g_xm[idx] = s * (1.0f / (float)NN);
}

// ---------------------------------------------------------------------------
// Kernel: router logits, softmax, top-2, aux loss. Single block, 256 thr.
// ---------------------------------------------------------------------------
__global__ void k_router(const float* __restrict__ rw, float* __restrict__ out,
                         long long aux_idx, int has_aux) {
    __shared__ float probs[BB][EE];
    __shared__ int   top1s[BB];
    __shared__ float partial[EE];
    int t = threadIdx.x;

    {
        int b = t >> 3, e = t & 7;
        const float* xm = g_xm + b * DD;
        const float* w  = rw + e * DD;
        float s = 0.0f;
        #pragma unroll 8
        for (int d = 0; d < DD; d++) s += xm[d] * w[d];
        probs[b][e] = s;
    }
    __syncthreads();

    if (t < BB) {
        float l[EE];
        float mx = -1e30f;
        #pragma unroll
        for (int e = 0; e < EE; e++) { l[e] = probs[t][e]; mx = fmaxf(mx, l[e]); }
        float sum = 0.0f;
        #pragma unroll
        for (int e = 0; e < EE; e++) { l[e] = expf(l[e] - mx); sum += l[e]; }
        float inv = 1.0f / sum;
        #pragma unroll
        for (int e = 0; e < EE; e++) { l[e] *= inv; probs[t][e] = l[e]; }
        int i0 = 0; float v0 = l[0];
        #pragma unroll
        for (int e = 1; e < EE; e++) if (l[e] > v0) { v0 = l[e]; i0 = e; }
        int i1 = -1; float v1 = -1e30f;
        #pragma unroll
        for (int e = 0; e < EE; e++) if (e != i0 && l[e] > v1) { v1 = l[e]; i1 = e; }
        float inv01 = 1.0f / (v0 + v1);
        g_pair_e[2 * t]     = i0; g_pair_w[2 * t]     = v0 * inv01;
        g_pair_e[2 * t + 1] = i1; g_pair_w[2 * t + 1] = v1 * inv01;
        top1s[t] = i0;
    }
    __syncthreads();

    if (t < EE) {
        float ps = 0.0f; int c = 0;
        for (int b = 0; b < BB; b++) { ps += probs[b][t]; c += (top1s[b] == t); }
        partial[t] = ps * (float)c;
    }
    __syncthreads();

    if (t == 0 && has_aux) {
        float s = 0.0f;
        #pragma unroll
        for (int e = 0; e < EE; e++) s += partial[e];
        out[aux_idx] = s * ((float)EE / ((float)BB * (float)BB));
    }
}

// ---------------------------------------------------------------------------
// Fused conversion kernel: all fp32 -> fp16 conversions + x transpose.
// ---------------------------------------------------------------------------
#define NB_X   24576
#define NB_XT  24576
#define NB_TW1 16384
#define NB_TW2 16384
#define NB_CW1 9216
#define NB_CW2 9216
#define NB_TOTAL (NB_X + NB_XT + NB_TW1 + NB_TW2 + NB_CW1 + NB_CW2)

__device__ __forceinline__ void cvt4(const float* __restrict__ s, __half* d, int i) {
    float4 v = ((const float4*)s)[i];
    __half2 a = __floats2half2_rn(v.x, v.y);
    __half2 b = __floats2half2_rn(v.z, v.w);
    uint2 u;
    u.x = *reinterpret_cast<uint32_t*>(&a);
    u.y = *reinterpret_cast<uint32_t*>(&b);
    ((uint2*)d)[i] = u;
}

__global__ void k_convert(const float* __restrict__ x,
                          const float* __restrict__ tw1,
                          const float* __restrict__ tw2,
                          const float* __restrict__ cw1,
                          const float* __restrict__ cw2) {
    __shared__ float t[32][33];
    int bid = blockIdx.x;
    int tid = threadIdx.x;

    if (bid < NB_X) {
        cvt4(x, g_xf, bid * 256 + tid);
    } else if (bid < NB_X + NB_XT) {
        int r = bid - NB_X;
        int b = r / 768;
        int rem = r - b * 768;
        int nblk = rem / 24;
        int dblk = rem - nblk * 24;
        int d0 = dblk * 32, n0 = nblk * 32;
        int tx = tid & 31, ty = tid >> 5;
        #pragma unroll
        for (int i = 0; i < 4; i++) {
            int n = n0 + ty + i * 8;
            t[ty + i * 8][tx] = x[((size_t)b * NN + n) * DD + d0 + tx];
        }
        __syncthreads();
        #pragma unroll
        for (int i = 0; i < 4; i++) {
            int d = d0 + ty + i * 8;
            g_xtf[((size_t)b * DD + d) * NN + n0 + tx] =
                __float2half_rn(t[tx][ty + i * 8]);
        }
    } else if (bid < NB_X + NB_XT + NB_TW1) {
        cvt4(tw1, g_tw1f, (bid - NB_X - NB_XT) * 256 + tid);
    } else if (bid < NB_X + NB_XT + NB_TW1 + NB_TW2) {
        cvt4(tw2, g_tw2f, (bid - NB_X - NB_XT - NB_TW1) * 256 + tid);
    } else if (bid < NB_X + NB_XT + NB_TW1 + NB_TW2 + NB_CW1) {
        cvt4(cw1, g_cw1f, (bid - NB_X - NB_XT - NB_TW1 - NB_TW2) * 256 + tid);
    } else {
        cvt4(cw2, g_cw2f, (bid - NB_X - NB_XT - NB_TW1 - NB_TW2 - NB_CW1) * 256 + tid);
    }
}

// ---------------------------------------------------------------------------
// WMMA fp16 GEMM core (round-9 proven shape): CTA 128x128, 128 threads =
// 4 warps (2x2), warp tile 64x64 (0.5 ldmatrix/MMA), BK=64, cp.async
// 2-stage. ~168 regs -> 3 CTAs/SM = 12 warps.
// mT/nT passed in (merged kernels decode their own tile mapping).
// BIAS: 1=per-col(n), 2=per-row(m). TOHALF: write fp16, else fp32.
// ---------------------------------------------------------------------------
#define BK 64
#define RSTR 144                      // bytes per smem row
#define STRDH 72                      // halves per smem row
#define A_TILE_B (128 * RSTR)         // 18432
#define STAGE_B (2 * A_TILE_B)        // 36864
#define SMEM_TOT (2 * STAGE_B)        // 73728

template<int Nn, int K, bool GELU, int BIAS, bool TOHALF>
__device__ __forceinline__ void wmma_core(
        int mT, int nT,
        const __half* A, const __half* B,
        const float* __restrict__ bias,
        float* Cf, __half* Ch) {
    extern __shared__ __align__(128) unsigned char dsm[];
    const uint32_t sbase = smem_u32(dsm);

    const int tid = threadIdx.x, lane = tid & 31, wid = tid >> 5;
    const int wm = wid & 1, wn = wid >> 1;    // 2 x 2 warp grid, 64x64 tiles

    wmma::fragment<wmma::accumulator, 16, 16, 16, float> acc[4][4];
    #pragma unroll
    for (int mt = 0; mt < 4; mt++)
        #pragma unroll
        for (int p = 0; p < 4; p++) wmma::fill_fragment(acc[mt][p], 0.0f);

    const __half* pA = A + (size_t)mT * K;
    const __half* pB = B + (size_t)nT * K;

    // Per stage: A 128 rows + B 128 rows, 8x16B chunks/row = 2048 chunks,
    // 16 per thread (128 threads).
    auto load_stage = [&](int stage, int chk) {
        uint32_t sb = sbase + stage * STAGE_B;
        #pragma unroll
        for (int it = 0; it < 8; it++) {           // A
            int idx = it * 128 + tid;
            int row = idx >> 3, c = idx & 7;
            CP_ASYNC16(sb + row * RSTR + c * 16,
                       pA + (size_t)row * K + chk * BK + c * 8);
        }
        #pragma unroll
        for (int it = 0; it < 8; it++) {           // B
            int idx = it * 128 + tid;
            int row = idx >> 3, c = idx & 7;
            CP_ASYNC16(sb + A_TILE_B + row * RSTR + c * 16,
                       pB + (size_t)row * K + chk * BK + c * 8);
        }
        CP_COMMIT();
    };

    const int NCH = K / BK;
    load_stage(0, 0);

    for (int chk = 0; chk < NCH; chk++) {
        if (chk + 1 < NCH) {
            load_stage((chk + 1) & 1, chk + 1);
            CP_WAIT1();
        } else {
            CP_WAIT0();
        }
        __syncthreads();

        __half* sA = (__half*)(dsm + (chk & 1) * STAGE_B);
        __half* sB = (__half*)(dsm + (chk & 1) * STAGE_B + A_TILE_B);

        #pragma unroll
        for (int ks = 0; ks < BK / 16; ks++) {
            wmma::fragment<wmma::matrix_a, 16, 16, 16, __half, wmma::row_major> af[4];
            wmma::fragment<wmma::matrix_b, 16, 16, 16, __half, wmma::col_major> bf[4];
            #pragma unroll
            for (int mt = 0; mt < 4; mt++)
                wmma::load_matrix_sync(af[mt], &sA[(wm * 64 + mt * 16) * STRDH + ks * 16], STRDH);
            #pragma unroll
            for (int p = 0; p < 4; p++)
                wmma::load_matrix_sync(bf[p], &sB[(wn * 64 + p * 16) * STRDH + ks * 16], STRDH);
            #pragma unroll
            for (int mt = 0; mt < 4; mt++)
                #pragma unroll
                for (int p = 0; p < 4; p++)
                    wmma::mma_sync(acc[mt][p], af[mt], bf[p], acc[mt][p]);
        }
        __syncthreads();
    }

    // --- epilogue via per-warp 16x16 fp32 staging (smem reuse) ---
    float* st = (float*)dsm + wid * 288;
    const int r  = lane >> 1;        // 0..15
    const int c0 = (lane & 1) * 8;   // 0 or 8
    #pragma unroll
    for (int mt = 0; mt < 4; mt++) {
        #pragma unroll
        for (int p = 0; p < 4; p++) {
            wmma::store_matrix_sync(st, acc[mt][p], 16, wmma::mem_row_major);
            __syncwarp();
            int row = mT + wm * 64 + mt * 16 + r;
            int col = nT + wn * 64 + p * 16 + c0;
            float v[8];
            #pragma unroll
            for (int j = 0; j < 8; j++) v[j] = st[r * 16 + c0 + j];
            if (BIAS == 1) {
                #pragma unroll
                for (int j = 0; j < 8; j++) v[j] += __ldg(&bias[col + j]);
            } else if (BIAS == 2) {
                float rb = __ldg(&bias[row]);
                #pragma unroll
                for (int j = 0; j < 8; j++) v[j] += rb;
            }
            if (GELU) {
                #pragma unroll
                for (int j = 0; j < 8; j++) v[j] = gelu_tanh(v[j]);
            }
            if (TOHALF) {
                __half2 hv[4];
                #pragma unroll
                for (int j = 0; j < 4; j++)
                    hv[j] = __floats2half2_rn(v[2 * j], v[2 * j + 1]);
                *(uint4*)(Ch + (size_t)row * Nn + col) = *(uint4*)hv;
            } else {
                *(float4*)(Cf + (size_t)row * Nn + col)     = *(float4*)&v[0];
                *(float4*)(Cf + (size_t)row * Nn + col + 4) = *(float4*)&v[4];
            }
            __syncwarp();
        }
    }
}

// ---------------------------------------------------------------------------
// Merged L1 kernel: token + channel first layers in one launch.
// grid (192, 1, NPAIR): token pairs tile 6(m) x 32(n); channel 8 x 24.
// ---------------------------------------------------------------------------
__global__ void __launch_bounds__(128, 3)
k_l1(const float* __restrict__ tb1, const float* __restrict__ cb1) {
    int p = blockIdx.z;
    int e = g_pair_e[p];
    int b = p >> 1;
    int bx = blockIdx.x;
    if (e < E_TOKN) {
        // H[p][d][h] = gelu( sum_n xT[b][d][n] * tw1[e][h][n] + b1[e][h] )
        int mt = bx % 6, nt = bx / 6;          // M=DD(6) x N=HNN(32)
        wmma_core<HNN, NN, true, 1, true>(
            mt * 128, nt * 128,
            g_xtf + (size_t)b * DD * NN,
            g_tw1f + (size_t)e * HNN * NN,
            tb1 + e * HNN,
            nullptr, g_hidf + (size_t)p * HID_ELEMS);
    } else {
        int ec = e - E_TOKN;
        // G[p][n][h] = gelu( sum_d x[b][n][d] * cw1[e][h][d] + b1[e][h] )
        int mt = bx % 8, nt = bx / 8;          // M=NN(8) x N=HDD(24)
        wmma_core<HDD, DD, true, 1, true>(
            mt * 128, nt * 128,
            g_xf + (size_t)b * NN * DD,
            g_cw1f + (size_t)ec * HDD * DD,
            cb1 + ec * HDD,
            nullptr, g_hidf + (size_t)p * HID_ELEMS);
    }
}

// ---------------------------------------------------------------------------
// Merged L2 kernel: token + channel second layers. grid (48, 1, NPAIR);
// both variants tile M=NN(8) x N=DD(6).
// ---------------------------------------------------------------------------
__global__ void __launch_bounds__(128, 3)
k_l2(const float* __restrict__ tb2, const float* __restrict__ cb2) {
    int p = blockIdx.z;
    int e = g_pair_e[p];
    int bx = blockIdx.x;
    int mt = bx % 8, nt = bx / 8;
    if (e < E_TOKN) {
        // contrib[p][n][d] = sum_h tw2[e][n][h] * H[p][d][h] + b2[e][n]
        wmma_core<DD, HNN, false, 2, false>(
            mt * 128, nt * 128,
            g_tw2f + (size_t)e * NN * HNN,
            g_hidf + (size_t)p * HID_ELEMS,
            tb2 + e * NN,
            g_contrib + (size_t)p * CON_ELEMS, nullptr);
    } else {
        int ec = e - E_TOKN;
        // contrib[p][n][d] = sum_h G[p][n][h] * cw2[e][d][h] + b2[e][d]
        wmma_core<DD, HDD, false, 1, false>(
            mt * 128, nt * 128,
            g_hidf + (size_t)p * HID_ELEMS,
            g_cw2f + (size_t)ec * DD * HDD,
            cb2 + ec * DD,
            g_contrib + (size_t)p * CON_ELEMS, nullptr);
    }
}

// ---------------------------------------------------------------------------
// Final combine
// ---------------------------------------------------------------------------
__global__ void k_combine(float* __restrict__ out) {
    long long idx = (long long)blockIdx.x * 256 + threadIdx.x;
    if (idx >= (long long)BB * NN * DD) return;
    int b = (int)(idx / (NN * DD));
    int r = (int)(idx - (long long)b * (NN * DD));
    float v0 = g_pair_w[2 * b]     * g_contrib[(size_t)(2 * b) * CON_ELEMS + r];
    float v1 = g_pair_w[2 * b + 1] * g_contrib[(size_t)(2 * b + 1) * CON_ELEMS + r];
    out[idx] = v0 + v1;
}

// ---------------------------------------------------------------------------
// Launch — only harness pointers cross host->device. ncu capture lands on
// launch index 3 = merged k_l1.
// ---------------------------------------------------------------------------
extern "C" void kernel_launch(void* const* d_in, const int* in_sizes, int n_in,
                              void* d_out, int out_size) {
    const float* x        = (const float*)d_in[0];
    const float* router_w = (const float*)d_in[1];
    const float* tok_w1   = (const float*)d_in[2];
    const float* tok_b1   = (const float*)d_in[3];
    const float* tok_w2   = (const float*)d_in[4];
    const float* tok_b2   = (const float*)d_in[5];
    const float* ch_w1    = (const float*)d_in[6];
    const float* ch_b1    = (const float*)d_in[7];
    const float* ch_w2    = (const float*)d_in[8];
    const float* ch_b2    = (const float*)d_in[9];
    float* out = (float*)d_out;

    long long bnd = (long long)BB * NN * DD;
    int has_aux = (long long)out_size > bnd;

    cudaFuncSetAttribute(k_l1, cudaFuncAttributeMaxDynamicSharedMemorySize, SMEM_TOT);
    cudaFuncSetAttribute(k_l2, cudaFuncAttributeMaxDynamicSharedMemorySize, SMEM_TOT);

    // 0: mean, 1: router, 2: fused conversions
    k_mean<<<(BB * DD + 255) / 256, 256>>>(x);
    k_router<<<1, 256>>>(router_w, out, bnd, has_aux);
    k_convert<<<NB_TOTAL, 256>>>(x, tok_w1, tok_w2, ch_w1, ch_w2);

    // 3: merged L1 GEMM (token 6x32 tiles, channel 8x24 tiles -> both 192)
    dim3 g_l1(192, 1, NPAIR);
    k_l1<<<g_l1, 128, SMEM_TOT>>>(tok_b1, ch_b1);

    // 4: merged L2 GEMM (both 8x6 = 48 tiles)
    dim3 g_l2g(48, 1, NPAIR);
    k_l2<<<g_l2g, 128, SMEM_TOT>>>(tok_b2, ch_b2);

    // 5: combine
    k_combine<<<(unsigned)((bnd + 255) / 256), 256>>>(out);
}

// round 12
// speedup vs baseline: 1.0959x; 1.0363x over previous
#include <cuda_runtime.h>
#include <cuda_fp16.h>
#include <mma.h>
#include <math.h>
#include <stdint.h>

using namespace nvcuda;

// ---------------------------------------------------------------------------
// Problem constants
// ---------------------------------------------------------------------------
#define BB 32
#define NN 1024
#define DD 768
#define E_TOKN 4
#define E_CHN 4
#define EE 8
#define TOPK 2
#define HNN 4096
#define HDD 3072
#define NPAIR (BB * TOPK)            // 64 selected (batch, expert) pairs
#define HID_ELEMS (DD * HNN)         // 3145728 == NN*HDD
#define CON_ELEMS (NN * DD)          // 786432

// ---------------------------------------------------------------------------
// Static device scratch (uint4-typed: guaranteed 16B alignment).
// RULE (rounds 3-5 root cause): device-global addresses are formed ONLY in
// device code — host-side g_* is the shadow symbol (ATS makes it writable!).
// ---------------------------------------------------------------------------
__device__ float g_xm[BB * DD];
__device__ int   g_pair_e[NPAIR];
__device__ float g_pair_w[NPAIR];

__device__ uint4 g_xf_raw  [BB * NN * DD / 8];          // x fp16 [b][n][d]
__device__ uint4 g_xtf_raw [BB * DD * NN / 8];          // x^T fp16 [b][d][n]
__device__ uint4 g_tw1f_raw[E_TOKN * HNN * NN / 8];
__device__ uint4 g_tw2f_raw[E_TOKN * NN * HNN / 8];
__device__ uint4 g_cw1f_raw[E_CHN * HDD * DD / 8];
__device__ uint4 g_cw2f_raw[E_CHN * DD * HDD / 8];
__device__ uint4 g_hidf_raw[(size_t)NPAIR * HID_ELEMS / 8];   // ~402 MB fp16
__device__ float4 g_contrib_raw[(size_t)NPAIR * CON_ELEMS / 4]; // ~201 MB

#define g_xf   ((__half*)g_xf_raw)
#define g_xtf  ((__half*)g_xtf_raw)
#define g_tw1f ((__half*)g_tw1f_raw)
#define g_tw2f ((__half*)g_tw2f_raw)
#define g_cw1f ((__half*)g_cw1f_raw)
#define g_cw2f ((__half*)g_cw2f_raw)
#define g_hidf ((__half*)g_hidf_raw)
#define g_contrib ((float*)g_contrib_raw)

// ---------------------------------------------------------------------------
// Helpers
// ---------------------------------------------------------------------------
__device__ __forceinline__ float gelu_tanh(float v) {
    const float c = 0.7978845608028654f; // sqrt(2/pi)
    float u = c * (v + 0.044715f * v * v * v);
    return 0.5f * v * (1.0f + tanhf(u));
}

// 2-wide gelu using tanh.approx.f16x2 (1 MUFU op per 2 elems instead of 2).
__device__ __forceinline__ __half2 gelu2_h(float a, float b) {
    const float c = 0.7978845608028654f;
    float ua = c * (a + 0.044715f * a * a * a);
    float ub = c * (b + 0.044715f * b * b * b);
    __half2 u2 = __floats2half2_rn(ua, ub);
    uint32_t uu = *reinterpret_cast<uint32_t*>(&u2);
    uint32_t tt;
    asm("tanh.approx.f16x2 %0, %1;" : "=r"(tt) : "r"(uu));
    __half2 t2 = *reinterpret_cast<__half2*>(&tt);
    __half2 vh = __floats2half2_rn(a, b);
    __half2 one  = __float2half2_rn(1.0f);
    __half2 half_ = __float2half2_rn(0.5f);
    return __hmul2(__hmul2(half_, vh), __hadd2(one, t2));
}

__device__ __forceinline__ uint32_t smem_u32(const void* p) {
    uint32_t a;
    asm("{ .reg .u64 t; cvta.to.shared.u64 t, %1; cvt.u32.u64 %0, t; }"
        : "=r"(a) : "l"(p));
    return a;
}

#define CP_ASYNC16(dst32, src) \
    asm volatile("cp.async.cg.shared.global [%0], [%1], 16;" \
                 :: "r"(dst32), "l"(src) : "memory")
#define CP_COMMIT()  asm volatile("cp.async.commit_group;" ::: "memory")
#define CP_WAIT0()   asm volatile("cp.async.wait_group 0;" ::: "memory")
#define CP_WAIT1()   asm volatile("cp.async.wait_group 1;" ::: "memory")

// ---------------------------------------------------------------------------
// Kernel: xm[b,d] = mean_n x[b,n,d]
// ---------------------------------------------------------------------------
__global__ void k_mean(const float* __restrict__ x) {
    int idx = blockIdx.x * blockDim.x + threadIdx.x;
    if (idx >= BB * DD) return;
    int b = idx / DD;
    int d = idx - b * DD;
    const float* p = x + (size_t)b * NN * DD + d;
    float s = 0.0f;
    #pragma unroll 8
    for (int n = 0; n < NN; n++) s += p[(size_t)n * DD];
    g_xm[idx] = s * (1.0f / (float)NN);
}

// ---------------------------------------------------------------------------
// Kernel: router logits, softmax, top-2, aux loss. Single block, 256 thr.
// ---------------------------------------------------------------------------
__global__ void k_router(const float* __restrict__ rw, float* __restrict__ out,
                         long long aux_idx, int has_aux) {
    __shared__ float probs[BB][EE];
    __shared__ int   top1s[BB];
    __shared__ float partial[EE];
    int t = threadIdx.x;

    {
        int b = t >> 3, e = t & 7;
        const float* xm = g_xm + b * DD;
        const float* w  = rw + e * DD;
        float s = 0.0f;
        #pragma unroll 8
        for (int d = 0; d < DD; d++) s += xm[d] * w[d];
        probs[b][e] = s;
    }
    __syncthreads();

    if (t < BB) {
        float l[EE];
        float mx = -1e30f;
        #pragma unroll
        for (int e = 0; e < EE; e++) { l[e] = probs[t][e]; mx = fmaxf(mx, l[e]); }
        float sum = 0.0f;
        #pragma unroll
        for (int e = 0; e < EE; e++) { l[e] = expf(l[e] - mx); sum += l[e]; }
        float inv = 1.0f / sum;
        #pragma unroll
        for (int e = 0; e < EE; e++) { l[e] *= inv; probs[t][e] = l[e]; }
        int i0 = 0; float v0 = l[0];
        #pragma unroll
        for (int e = 1; e < EE; e++) if (l[e] > v0) { v0 = l[e]; i0 = e; }
        int i1 = -1; float v1 = -1e30f;
        #pragma unroll
        for (int e = 0; e < EE; e++) if (e != i0 && l[e] > v1) { v1 = l[e]; i1 = e; }
        float inv01 = 1.0f / (v0 + v1);
        g_pair_e[2 * t]     = i0; g_pair_w[2 * t]     = v0 * inv01;
        g_pair_e[2 * t + 1] = i1; g_pair_w[2 * t + 1] = v1 * inv01;
        top1s[t] = i0;
    }
    __syncthreads();

    if (t < EE) {
        float ps = 0.0f; int c = 0;
        for (int b = 0; b < BB; b++) { ps += probs[b][t]; c += (top1s[b] == t); }
        partial[t] = ps * (float)c;
    }
    __syncthreads();

    if (t == 0 && has_aux) {
        float s = 0.0f;
        #pragma unroll
        for (int e = 0; e < EE; e++) s += partial[e];
        out[aux_idx] = s * ((float)EE / ((float)BB * (float)BB));
    }
}

// ---------------------------------------------------------------------------
// Fused conversion kernel: all fp32 -> fp16 conversions + x transpose.
// ---------------------------------------------------------------------------
#define NB_X   24576
#define NB_XT  24576
#define NB_TW1 16384
#define NB_TW2 16384
#define NB_CW1 9216
#define NB_CW2 9216
#define NB_TOTAL (NB_X + NB_XT + NB_TW1 + NB_TW2 + NB_CW1 + NB_CW2)

__device__ __forceinline__ void cvt4(const float* __restrict__ s, __half* d, int i) {
    float4 v = ((const float4*)s)[i];
    __half2 a = __floats2half2_rn(v.x, v.y);
    __half2 b = __floats2half2_rn(v.z, v.w);
    uint2 u;
    u.x = *reinterpret_cast<uint32_t*>(&a);
    u.y = *reinterpret_cast<uint32_t*>(&b);
    ((uint2*)d)[i] = u;
}

__global__ void k_convert(const float* __restrict__ x,
                          const float* __restrict__ tw1,
                          const float* __restrict__ tw2,
                          const float* __restrict__ cw1,
                          const float* __restrict__ cw2) {
    __shared__ float t[32][33];
    int bid = blockIdx.x;
    int tid = threadIdx.x;

    if (bid < NB_X) {
        cvt4(x, g_xf, bid * 256 + tid);
    } else if (bid < NB_X + NB_XT) {
        int r = bid - NB_X;
        int b = r / 768;
        int rem = r - b * 768;
        int nblk = rem / 24;
        int dblk = rem - nblk * 24;
        int d0 = dblk * 32, n0 = nblk * 32;
        int tx = tid & 31, ty = tid >> 5;
        #pragma unroll
        for (int i = 0; i < 4; i++) {
            int n = n0 + ty + i * 8;
            t[ty + i * 8][tx] = x[((size_t)b * NN + n) * DD + d0 + tx];
        }
        __syncthreads();
        #pragma unroll
        for (int i = 0; i < 4; i++) {
            int d = d0 + ty + i * 8;
            g_xtf[((size_t)b * DD + d) * NN + n0 + tx] =
                __float2half_rn(t[tx][ty + i * 8]);
        }
    } else if (bid < NB_X + NB_XT + NB_TW1) {
        cvt4(tw1, g_tw1f, (bid - NB_X - NB_XT) * 256 + tid);
    } else if (bid < NB_X + NB_XT + NB_TW1 + NB_TW2) {
        cvt4(tw2, g_tw2f, (bid - NB_X - NB_XT - NB_TW1) * 256 + tid);
    } else if (bid < NB_X + NB_XT + NB_TW1 + NB_TW2 + NB_CW1) {
        cvt4(cw1, g_cw1f, (bid - NB_X - NB_XT - NB_TW1 - NB_TW2) * 256 + tid);
    } else {
        cvt4(cw2, g_cw2f, (bid - NB_X - NB_XT - NB_TW1 - NB_TW2 - NB_CW1) * 256 + tid);
    }
}

// ---------------------------------------------------------------------------
// WMMA fp16 GEMM core (round-9 proven shape): CTA 128x128, 128 threads =
// 4 warps (2x2), warp tile 64x64 (0.5 ldmatrix/MMA), BK=64, cp.async
// 2-stage. ~168 regs -> 3 CTAs/SM = 12 warps.
// GELU epilogue uses tanh.approx.f16x2 (half the MUFU ops).
// BIAS: 1=per-col(n), 2=per-row(m). TOHALF: write fp16, else fp32.
// ---------------------------------------------------------------------------
#define BK 64
#define RSTR 144                      // bytes per smem row
#define STRDH 72                      // halves per smem row
#define A_TILE_B (128 * RSTR)         // 18432
#define STAGE_B (2 * A_TILE_B)        // 36864
#define SMEM_TOT (2 * STAGE_B)        // 73728

template<int Nn, int K, bool GELU, int BIAS, bool TOHALF>
__device__ __forceinline__ void wmma_core(
        int mT, int nT,
        const __half* A, const __half* B,
        const float* __restrict__ bias,
        float* Cf, __half* Ch) {
    extern __shared__ __align__(128) unsigned char dsm[];
    const uint32_t sbase = smem_u32(dsm);

    const int tid = threadIdx.x, lane = tid & 31, wid = tid >> 5;
    const int wm = wid & 1, wn = wid >> 1;    // 2 x 2 warp grid, 64x64 tiles

    wmma::fragment<wmma::accumulator, 16, 16, 16, float> acc[4][4];
    #pragma unroll
    for (int mt = 0; mt < 4; mt++)
        #pragma unroll
        for (int p = 0; p < 4; p++) wmma::fill_fragment(acc[mt][p], 0.0f);

    const __half* pA = A + (size_t)mT * K;
    const __half* pB = B + (size_t)nT * K;

    auto load_stage = [&](int stage, int chk) {
        uint32_t sb = sbase + stage * STAGE_B;
        #pragma unroll
        for (int it = 0; it < 8; it++) {           // A
            int idx = it * 128 + tid;
            int row = idx >> 3, c = idx & 7;
            CP_ASYNC16(sb + row * RSTR + c * 16,
                       pA + (size_t)row * K + chk * BK + c * 8);
        }
        #pragma unroll
        for (int it = 0; it < 8; it++) {           // B
            int idx = it * 128 + tid;
            int row = idx >> 3, c = idx & 7;
            CP_ASYNC16(sb + A_TILE_B + row * RSTR + c * 16,
                       pB + (size_t)row * K + chk * BK + c * 8);
        }
        CP_COMMIT();
    };

    const int NCH = K / BK;
    load_stage(0, 0);

    for (int chk = 0; chk < NCH; chk++) {
        if (chk + 1 < NCH) {
            load_stage((chk + 1) & 1, chk + 1);
            CP_WAIT1();
        } else {
            CP_WAIT0();
        }
        __syncthreads();

        __half* sA = (__half*)(dsm + (chk & 1) * STAGE_B);
        __half* sB = (__half*)(dsm + (chk & 1) * STAGE_B + A_TILE_B);

        #pragma unroll
        for (int ks = 0; ks < BK / 16; ks++) {
            wmma::fragment<wmma::matrix_a, 16, 16, 16, __half, wmma::row_major> af[4];
            wmma::fragment<wmma::matrix_b, 16, 16, 16, __half, wmma::col_major> bf[4];
            #pragma unroll
            for (int mt = 0; mt < 4; mt++)
                wmma::load_matrix_sync(af[mt], &sA[(wm * 64 + mt * 16) * STRDH + ks * 16], STRDH);
            #pragma unroll
            for (int p = 0; p < 4; p++)
                wmma::load_matrix_sync(bf[p], &sB[(wn * 64 + p * 16) * STRDH + ks * 16], STRDH);
            #pragma unroll
            for (int mt = 0; mt < 4; mt++)
                #pragma unroll
                for (int p = 0; p < 4; p++)
                    wmma::mma_sync(acc[mt][p], af[mt], bf[p], acc[mt][p]);
        }
        __syncthreads();
    }

    // --- epilogue via per-warp 16x16 fp32 staging (smem reuse) ---
    float* st = (float*)dsm + wid * 288;
    const int r  = lane >> 1;        // 0..15
    const int c0 = (lane & 1) * 8;   // 0 or 8
    #pragma unroll
    for (int mt = 0; mt < 4; mt++) {
        #pragma unroll
        for (int p = 0; p < 4; p++) {
            wmma::store_matrix_sync(st, acc[mt][p], 16, wmma::mem_row_major);
            __syncwarp();
            int row = mT + wm * 64 + mt * 16 + r;
            int col = nT + wn * 64 + p * 16 + c0;
            float v[8];
            #pragma unroll
            for (int j = 0; j < 8; j++) v[j] = st[r * 16 + c0 + j];
            if (BIAS == 1) {
                #pragma unroll
                for (int j = 0; j < 8; j++) v[j] += __ldg(&bias[col + j]);
            } else if (BIAS == 2) {
                float rb = __ldg(&bias[row]);
                #pragma unroll
                for (int j = 0; j < 8; j++) v[j] += rb;
            }
            if (TOHALF) {
                __half2 hv[4];
                if (GELU) {
                    #pragma unroll
                    for (int j = 0; j < 4; j++)
                        hv[j] = gelu2_h(v[2 * j], v[2 * j + 1]);
                } else {
                    #pragma unroll
                    for (int j = 0; j < 4; j++)
                        hv[j] = __floats2half2_rn(v[2 * j], v[2 * j + 1]);
                }
                *(uint4*)(Ch + (size_t)row * Nn + col) = *(uint4*)hv;
            } else {
                if (GELU) {
                    #pragma unroll
                    for (int j = 0; j < 8; j++) v[j] = gelu_tanh(v[j]);
                }
                *(float4*)(Cf + (size_t)row * Nn + col)     = *(float4*)&v[0];
                *(float4*)(Cf + (size_t)row * Nn + col + 4) = *(float4*)&v[4];
            }
            __syncwarp();
        }
    }
}

// ---------------------------------------------------------------------------
// Merged L1 kernel: token + channel first layers in one launch.
// grid (192, 1, NPAIR): token pairs tile 6(m) x 32(n); channel 8 x 24.
// ---------------------------------------------------------------------------
__global__ void __launch_bounds__(128, 3)
k_l1(const float* __restrict__ tb1, const float* __restrict__ cb1) {
    int p = blockIdx.z;
    int e = g_pair_e[p];
    int b = p >> 1;
    int bx = blockIdx.x;
    if (e < E_TOKN) {
        // H[p][d][h] = gelu( sum_n xT[b][d][n] * tw1[e][h][n] + b1[e][h] )
        int mt = bx % 6, nt = bx / 6;          // M=DD(6) x N=HNN(32)
        wmma_core<HNN, NN, true, 1, true>(
            mt * 128, nt * 128,
            g_xtf + (size_t)b * DD * NN,
            g_tw1f + (size_t)e * HNN * NN,
            tb1 + e * HNN,
            nullptr, g_hidf + (size_t)p * HID_ELEMS);
    } else {
        int ec = e - E_TOKN;
        // G[p][n][h] = gelu( sum_d x[b][n][d] * cw1[e][h][d] + b1[e][h] )
        int mt = bx % 8, nt = bx / 8;          // M=NN(8) x N=HDD(24)
        wmma_core<HDD, DD, true, 1, true>(
            mt * 128, nt * 128,
            g_xf + (size_t)b * NN * DD,
            g_cw1f + (size_t)ec * HDD * DD,
            cb1 + ec * HDD,
            nullptr, g_hidf + (size_t)p * HID_ELEMS);
    }
}

// ---------------------------------------------------------------------------
// Merged L2 kernel: token + channel second layers. grid (48, 1, NPAIR);
// both variants tile M=NN(8) x N=DD(6).
// ---------------------------------------------------------------------------
__global__ void __launch_bounds__(128, 3)
k_l2(const float* __restrict__ tb2, const float* __restrict__ cb2) {
    int p = blockIdx.z;
    int e = g_pair_e[p];
    int bx = blockIdx.x;
    int mt = bx % 8, nt = bx / 8;
    if (e < E_TOKN) {
        // contrib[p][n][d] = sum_h tw2[e][n][h] * H[p][d][h] + b2[e][n]
        wmma_core<DD, HNN, false, 2, false>(
            mt * 128, nt * 128,
            g_tw2f + (size_t)e * NN * HNN,
            g_hidf + (size_t)p * HID_ELEMS,
            tb2 + e * NN,
            g_contrib + (size_t)p * CON_ELEMS, nullptr);
    } else {
        int ec = e - E_TOKN;
        // contrib[p][n][d] = sum_h G[p][n][h] * cw2[e][d][h] + b2[e][d]
        wmma_core<DD, HDD, false, 1, false>(
            mt * 128, nt * 128,
            g_hidf + (size_t)p * HID_ELEMS,
            g_cw2f + (size_t)ec * DD * HDD,
            cb2 + ec * DD,
            g_contrib + (size_t)p * CON_ELEMS, nullptr);
    }
}

// ---------------------------------------------------------------------------
// Final combine
// ---------------------------------------------------------------------------
__global__ void k_combine(float* __restrict__ out) {
    long long idx = (long long)blockIdx.x * 256 + threadIdx.x;
    if (idx >= (long long)BB * NN * DD) return;
    int b = (int)(idx / (NN * DD));
    int r = (int)(idx - (long long)b * (NN * DD));
    float v0 = g_pair_w[2 * b]     * g_contrib[(size_t)(2 * b) * CON_ELEMS + r];
    float v1 = g_pair_w[2 * b + 1] * g_contrib[(size_t)(2 * b + 1) * CON_ELEMS + r];
    out[idx] = v0 + v1;
}

// ---------------------------------------------------------------------------
// Launch — only harness pointers cross host->device. ncu capture lands on
// launch index 3 = merged k_l1.
// ---------------------------------------------------------------------------
extern "C" void kernel_launch(void* const* d_in, const int* in_sizes, int n_in,
                              void* d_out, int out_size) {
    const float* x        = (const float*)d_in[0];
    const float* router_w = (const float*)d_in[1];
    const float* tok_w1   = (const float*)d_in[2];
    const float* tok_b1   = (const float*)d_in[3];
    const float* tok_w2   = (const float*)d_in[4];
    const float* tok_b2   = (const float*)d_in[5];
    const float* ch_w1    = (const float*)d_in[6];
    const float* ch_b1    = (const float*)d_in[7];
    const float* ch_w2    = (const float*)d_in[8];
    const float* ch_b2    = (const float*)d_in[9];
    float* out = (float*)d_out;

    long long bnd = (long long)BB * NN * DD;
    int has_aux = (long long)out_size > bnd;

    cudaFuncSetAttribute(k_l1, cudaFuncAttributeMaxDynamicSharedMemorySize, SMEM_TOT);
    cudaFuncSetAttribute(k_l2, cudaFuncAttributeMaxDynamicSharedMemorySize, SMEM_TOT);

    // 0: mean, 1: router, 2: fused conversions
    k_mean<<<(BB * DD + 255) / 256, 256>>>(x);
    k_router<<<1, 256>>>(router_w, out, bnd, has_aux);
    k_convert<<<NB_TOTAL, 256>>>(x, tok_w1, tok_w2, ch_w1, ch_w2);

    // 3: merged L1 GEMM (token 6x32 tiles, channel 8x24 tiles -> both 192)
    dim3 g_l1(192, 1, NPAIR);
    k_l1<<<g_l1, 128, SMEM_TOT>>>(tok_b1, ch_b1);

    // 4: merged L2 GEMM (both 8x6 = 48 tiles)
    dim3 g_l2g(48, 1, NPAIR);
    k_l2<<<g_l2g, 128, SMEM_TOT>>>(tok_b2, ch_b2);

    // 5: combine
    k_combine<<<(unsigned)((bnd + 255) / 256), 256>>>(out);
}

// round 13
// speedup vs baseline: 1.0965x; 1.0005x over previous
#include <cuda_runtime.h>
#include <cuda_fp16.h>
#include <mma.h>
#include <math.h>
#include <stdint.h>

using namespace nvcuda;

// ---------------------------------------------------------------------------
// Problem constants
// ---------------------------------------------------------------------------
#define BB 32
#define NN 1024
#define DD 768
#define E_TOKN 4
#define E_CHN 4
#define EE 8
#define TOPK 2
#define HNN 4096
#define HDD 3072
#define NPAIR (BB * TOPK)            // 64 selected (batch, expert) pairs
#define HID_ELEMS (DD * HNN)         // 3145728 == NN*HDD
#define CON_ELEMS (NN * DD)          // 786432

// ---------------------------------------------------------------------------
// Static device scratch (uint4-typed: guaranteed 16B alignment).
// RULE (rounds 3-5 root cause): device-global addresses are formed ONLY in
// device code — host-side g_* is the shadow symbol (ATS makes it writable!).
// ---------------------------------------------------------------------------
__device__ float g_xm[BB * DD];
__device__ int   g_pair_e[NPAIR];
__device__ float g_pair_w[NPAIR];

__device__ uint4 g_xf_raw  [BB * NN * DD / 8];          // x fp16 [b][n][d]
__device__ uint4 g_xtf_raw [BB * DD * NN / 8];          // x^T fp16 [b][d][n]
__device__ uint4 g_tw1f_raw[E_TOKN * HNN * NN / 8];
__device__ uint4 g_tw2f_raw[E_TOKN * NN * HNN / 8];
__device__ uint4 g_cw1f_raw[E_CHN * HDD * DD / 8];
__device__ uint4 g_cw2f_raw[E_CHN * DD * HDD / 8];
__device__ uint4 g_hidf_raw[(size_t)NPAIR * HID_ELEMS / 8];   // ~402 MB fp16

#define g_xf   ((__half*)g_xf_raw)
#define g_xtf  ((__half*)g_xtf_raw)
#define g_tw1f ((__half*)g_tw1f_raw)
#define g_tw2f ((__half*)g_tw2f_raw)
#define g_cw1f ((__half*)g_cw1f_raw)
#define g_cw2f ((__half*)g_cw2f_raw)
#define g_hidf ((__half*)g_hidf_raw)

// ---------------------------------------------------------------------------
// Helpers
// ---------------------------------------------------------------------------
// 2-wide gelu using tanh.approx.f16x2, scaled by per-pair weight.
__device__ __forceinline__ __half2 gelu2_h_scaled(float a, float b, __half2 ws) {
    const float c = 0.7978845608028654f;
    float ua = c * (a + 0.044715f * a * a * a);
    float ub = c * (b + 0.044715f * b * b * b);
    __half2 u2 = __floats2half2_rn(ua, ub);
    uint32_t uu = *reinterpret_cast<uint32_t*>(&u2);
    uint32_t tt;
    asm("tanh.approx.f16x2 %0, %1;" : "=r"(tt) : "r"(uu));
    __half2 t2 = *reinterpret_cast<__half2*>(&tt);
    __half2 vh = __floats2half2_rn(a, b);
    __half2 one  = __float2half2_rn(1.0f);
    __half2 half_ = __float2half2_rn(0.5f);
    __half2 g = __hmul2(__hmul2(half_, vh), __hadd2(one, t2));
    return __hmul2(g, ws);
}

__device__ __forceinline__ uint32_t smem_u32(const void* p) {
    uint32_t a;
    asm("{ .reg .u64 t; cvta.to.shared.u64 t, %1; cvt.u32.u64 %0, t; }"
        : "=r"(a) : "l"(p));
    return a;
}

#define CP_ASYNC16(dst32, src) \
    asm volatile("cp.async.cg.shared.global [%0], [%1], 16;" \
                 :: "r"(dst32), "l"(src) : "memory")
#define CP_COMMIT()  asm volatile("cp.async.commit_group;" ::: "memory")
#define CP_WAIT0()   asm volatile("cp.async.wait_group 0;" ::: "memory")
#define CP_WAIT1()   asm volatile("cp.async.wait_group 1;" ::: "memory")

// ---------------------------------------------------------------------------
// Kernel: xm[b,d] = mean_n x[b,n,d]
// ---------------------------------------------------------------------------
__global__ void k_mean(const float* __restrict__ x) {
    int idx = blockIdx.x * blockDim.x + threadIdx.x;
    if (idx >= BB * DD) return;
    int b = idx / DD;
    int d = idx - b * DD;
    const float* p = x + (size_t)b * NN * DD + d;
    float s = 0.0f;
    #pragma unroll 8
    for (int n = 0; n < NN; n++) s += p[(size_t)n * DD];
    g_xm[idx] = s * (1.0f / (float)NN);
}

// ---------------------------------------------------------------------------
// Kernel: router logits, softmax, top-2, aux loss. Single block, 256 thr.
// ---------------------------------------------------------------------------
__global__ void k_router(const float* __restrict__ rw, float* __restrict__ out,
                         long long aux_idx, int has_aux) {
    __shared__ float probs[BB][EE];
    __shared__ int   top1s[BB];
    __shared__ float partial[EE];
    int t = threadIdx.x;

    {
        int b = t >> 3, e = t & 7;
        const float* xm = g_xm + b * DD;
        const float* w  = rw + e * DD;
        float s = 0.0f;
        #pragma unroll 8
        for (int d = 0; d < DD; d++) s += xm[d] * w[d];
        probs[b][e] = s;
    }
    __syncthreads();

    if (t < BB) {
        float l[EE];
        float mx = -1e30f;
        #pragma unroll
        for (int e = 0; e < EE; e++) { l[e] = probs[t][e]; mx = fmaxf(mx, l[e]); }
        float sum = 0.0f;
        #pragma unroll
        for (int e = 0; e < EE; e++) { l[e] = expf(l[e] - mx); sum += l[e]; }
        float inv = 1.0f / sum;
        #pragma unroll
        for (int e = 0; e < EE; e++) { l[e] *= inv; probs[t][e] = l[e]; }
        int i0 = 0; float v0 = l[0];
        #pragma unroll
        for (int e = 1; e < EE; e++) if (l[e] > v0) { v0 = l[e]; i0 = e; }
        int i1 = -1; float v1 = -1e30f;
        #pragma unroll
        for (int e = 0; e < EE; e++) if (e != i0 && l[e] > v1) { v1 = l[e]; i1 = e; }
        float inv01 = 1.0f / (v0 + v1);
        g_pair_e[2 * t]     = i0; g_pair_w[2 * t]     = v0 * inv01;
        g_pair_e[2 * t + 1] = i1; g_pair_w[2 * t + 1] = v1 * inv01;
        top1s[t] = i0;
    }
    __syncthreads();

    if (t < EE) {
        float ps = 0.0f; int c = 0;
        for (int b = 0; b < BB; b++) { ps += probs[b][t]; c += (top1s[b] == t); }
        partial[t] = ps * (float)c;
    }
    __syncthreads();

    if (t == 0 && has_aux) {
        float s = 0.0f;
        #pragma unroll
        for (int e = 0; e < EE; e++) s += partial[e];
        out[aux_idx] = s * ((float)EE / ((float)BB * (float)BB));
    }
}

// ---------------------------------------------------------------------------
// Fused conversion kernel: all fp32 -> fp16 conversions + x transpose.
// ---------------------------------------------------------------------------
#define NB_X   24576
#define NB_XT  24576
#define NB_TW1 16384
#define NB_TW2 16384
#define NB_CW1 9216
#define NB_CW2 9216
#define NB_TOTAL (NB_X + NB_XT + NB_TW1 + NB_TW2 + NB_CW1 + NB_CW2)

__device__ __forceinline__ void cvt4(const float* __restrict__ s, __half* d, int i) {
    float4 v = ((const float4*)s)[i];
    __half2 a = __floats2half2_rn(v.x, v.y);
    __half2 b = __floats2half2_rn(v.z, v.w);
    uint2 u;
    u.x = *reinterpret_cast<uint32_t*>(&a);
    u.y = *reinterpret_cast<uint32_t*>(&b);
    ((uint2*)d)[i] = u;
}

__global__ void k_convert(const float* __restrict__ x,
                          const float* __restrict__ tw1,
                          const float* __restrict__ tw2,
                          const float* __restrict__ cw1,
                          const float* __restrict__ cw2) {
    __shared__ float t[32][33];
    int bid = blockIdx.x;
    int tid = threadIdx.x;

    if (bid < NB_X) {
        cvt4(x, g_xf, bid * 256 + tid);
    } else if (bid < NB_X + NB_XT) {
        int r = bid - NB_X;
        int b = r / 768;
        int rem = r - b * 768;
        int nblk = rem / 24;
        int dblk = rem - nblk * 24;
        int d0 = dblk * 32, n0 = nblk * 32;
        int tx = tid & 31, ty = tid >> 5;
        #pragma unroll
        for (int i = 0; i < 4; i++) {
            int n = n0 + ty + i * 8;
            t[ty + i * 8][tx] = x[((size_t)b * NN + n) * DD + d0 + tx];
        }
        __syncthreads();
        #pragma unroll
        for (int i = 0; i < 4; i++) {
            int d = d0 + ty + i * 8;
            g_xtf[((size_t)b * DD + d) * NN + n0 + tx] =
                __float2half_rn(t[tx][ty + i * 8]);
        }
    } else if (bid < NB_X + NB_XT + NB_TW1) {
        cvt4(tw1, g_tw1f, (bid - NB_X - NB_XT) * 256 + tid);
    } else if (bid < NB_X + NB_XT + NB_TW1 + NB_TW2) {
        cvt4(tw2, g_tw2f, (bid - NB_X - NB_XT - NB_TW1) * 256 + tid);
    } else if (bid < NB_X + NB_XT + NB_TW1 + NB_TW2 + NB_CW1) {
        cvt4(cw1, g_cw1f, (bid - NB_X - NB_XT - NB_TW1 - NB_TW2) * 256 + tid);
    } else {
        cvt4(cw2, g_cw2f, (bid - NB_X - NB_XT - NB_TW1 - NB_TW2 - NB_CW1) * 256 + tid);
    }
}

// ---------------------------------------------------------------------------
// GEMM accumulation core (shared): adds A(128xK) * B(128xK)^T into acc.
// CTA 128x128, 128 threads = 4 warps (2x2), warp tile 64x64, BK=64,
// cp.async 2-stage double buffered. Callable multiple times per kernel:
// accumulator persists across calls (used by fused L2+combine).
// ---------------------------------------------------------------------------
#define BK 64
#define RSTR 144                      // bytes per smem row
#define STRDH 72                      // halves per smem row
#define A_TILE_B (128 * RSTR)         // 18432
#define STAGE_B (2 * A_TILE_B)        // 36864
#define SMEM_TOT (2 * STAGE_B)        // 73728

template<int K>
__device__ __forceinline__ void gemm_accum(
        wmma::fragment<wmma::accumulator, 16, 16, 16, float> (&acc)[4][4],
        const __half* pA, const __half* pB) {
    extern __shared__ __align__(128) unsigned char dsm[];
    const uint32_t sbase = smem_u32(dsm);
    const int tid = threadIdx.x, wid = tid >> 5;
    const int wm = wid & 1, wn = wid >> 1;    // 2 x 2 warp grid, 64x64 tiles

    auto load_stage = [&](int stage, int chk) {
        uint32_t sb = sbase + stage * STAGE_B;
        #pragma unroll
        for (int it = 0; it < 8; it++) {           // A
            int idx = it * 128 + tid;
            int row = idx >> 3, c = idx & 7;
            CP_ASYNC16(sb + row * RSTR + c * 16,
                       pA + (size_t)row * K + chk * BK + c * 8);
        }
        #pragma unroll
        for (int it = 0; it < 8; it++) {           // B
            int idx = it * 128 + tid;
            int row = idx >> 3, c = idx & 7;
            CP_ASYNC16(sb + A_TILE_B + row * RSTR + c * 16,
                       pB + (size_t)row * K + chk * BK + c * 8);
        }
        CP_COMMIT();
    };

    const int NCH = K / BK;
    load_stage(0, 0);

    for (int chk = 0; chk < NCH; chk++) {
        if (chk + 1 < NCH) {
            load_stage((chk + 1) & 1, chk + 1);
            CP_WAIT1();
        } else {
            CP_WAIT0();
        }
        __syncthreads();

        __half* sA = (__half*)(dsm + (chk & 1) * STAGE_B);
        __half* sB = (__half*)(dsm + (chk & 1) * STAGE_B + A_TILE_B);

        #pragma unroll
        for (int ks = 0; ks < BK / 16; ks++) {
            wmma::fragment<wmma::matrix_a, 16, 16, 16, __half, wmma::row_major> af[4];
            wmma::fragment<wmma::matrix_b, 16, 16, 16, __half, wmma::col_major> bf[4];
            #pragma unroll
            for (int mt = 0; mt < 4; mt++)
                wmma::load_matrix_sync(af[mt], &sA[(wm * 64 + mt * 16) * STRDH + ks * 16], STRDH);
            #pragma unroll
            for (int p = 0; p < 4; p++)
                wmma::load_matrix_sync(bf[p], &sB[(wn * 64 + p * 16) * STRDH + ks * 16], STRDH);
            #pragma unroll
            for (int mt = 0; mt < 4; mt++)
                #pragma unroll
                for (int p = 0; p < 4; p++)
                    wmma::mma_sync(acc[mt][p], af[mt], bf[p], acc[mt][p]);
        }
        __syncthreads();
    }
}

// ---------------------------------------------------------------------------
// Merged L1 kernel: token + channel first layers; hidden written as fp16
// PRE-SCALED by the pair's routing weight (enables fused L2+combine).
// grid (192, 1, NPAIR): token 6(m) x 32(n) tiles; channel 8 x 24.
// ---------------------------------------------------------------------------
__global__ void __launch_bounds__(128, 3)
k_l1(const float* __restrict__ tb1, const float* __restrict__ cb1) {
    int p = blockIdx.z;
    int e = g_pair_e[p];
    int b = p >> 1;
    int bx = blockIdx.x;
    float w = g_pair_w[p];

    wmma::fragment<wmma::accumulator, 16, 16, 16, float> acc[4][4];
    #pragma unroll
    for (int mt = 0; mt < 4; mt++)
        #pragma unroll
        for (int q = 0; q < 4; q++) wmma::fill_fragment(acc[mt][q], 0.0f);

    int mT, nT, Nn;
    const float* bias;
    if (e < E_TOKN) {
        // H[p][d][h] = w * gelu( sum_n xT[b][d][n] * tw1[e][h][n] + b1[e][h] )
        mT = (bx % 6) * 128; nT = (bx / 6) * 128; Nn = HNN;
        bias = tb1 + e * HNN;
        gemm_accum<NN>(acc,
            g_xtf + (size_t)b * DD * NN + (size_t)mT * NN,
            g_tw1f + (size_t)e * HNN * NN + (size_t)nT * NN);
    } else {
        int ec = e - E_TOKN;
        // G[p][n][h] = w * gelu( sum_d x[b][n][d] * cw1[e][h][d] + b1[e][h] )
        mT = (bx % 8) * 128; nT = (bx / 8) * 128; Nn = HDD;
        bias = cb1 + ec * HDD;
        gemm_accum<DD>(acc,
            g_xf + (size_t)b * NN * DD + (size_t)mT * DD,
            g_cw1f + (size_t)ec * HDD * DD + (size_t)nT * DD);
    }

    // --- epilogue: bias + gelu(f16x2 tanh) + weight scale -> fp16 hidden ---
    extern __shared__ __align__(128) unsigned char dsm[];
    const int tid = threadIdx.x, lane = tid & 31, wid = tid >> 5;
    const int wm = wid & 1, wn = wid >> 1;
    float* st = (float*)dsm + wid * 288;
    const int r  = lane >> 1;
    const int c0 = (lane & 1) * 8;
    __half2 ws = __float2half2_rn(w);
    __half* Ch = g_hidf + (size_t)p * HID_ELEMS;

    #pragma unroll
    for (int mt = 0; mt < 4; mt++) {
        #pragma unroll
        for (int q = 0; q < 4; q++) {
            wmma::store_matrix_sync(st, acc[mt][q], 16, wmma::mem_row_major);
            __syncwarp();
            int row = mT + wm * 64 + mt * 16 + r;
            int col = nT + wn * 64 + q * 16 + c0;
            float v[8];
            #pragma unroll
            for (int j = 0; j < 8; j++)
                v[j] = st[r * 16 + c0 + j] + __ldg(&bias[col + j]);
            __half2 hv[4];
            #pragma unroll
            for (int j = 0; j < 4; j++)
                hv[j] = gelu2_h_scaled(v[2 * j], v[2 * j + 1], ws);
            *(uint4*)(Ch + (size_t)row * Nn + col) = *(uint4*)hv;
            __syncwarp();
        }
    }
}

// ---------------------------------------------------------------------------
// Fused L2 + combine kernel: per batch b, BOTH selected pairs accumulate
// sequentially into one accumulator (hidden is pre-scaled by w), then the
// weight-combined bias is added and the result written straight to out.
// grid (48, 1, BB); tiles M=NN(8) x N=DD(6). Deterministic (no atomics).
// ---------------------------------------------------------------------------
__global__ void __launch_bounds__(128, 3)
k_l2out(const float* __restrict__ tb2, const float* __restrict__ cb2,
        float* __restrict__ out) {
    int b  = blockIdx.z;
    int bx = blockIdx.x;
    int mT = (bx % 8) * 128, nT = (bx / 8) * 128;

    wmma::fragment<wmma::accumulator, 16, 16, 16, float> acc[4][4];
    #pragma unroll
    for (int mt = 0; mt < 4; mt++)
        #pragma unroll
        for (int q = 0; q < 4; q++) wmma::fill_fragment(acc[mt][q], 0.0f);

    int   pe[2];
    float pw[2];
    #pragma unroll
    for (int i = 0; i < 2; i++) {
        int p = 2 * b + i;
        pe[i] = g_pair_e[p];
        pw[i] = g_pair_w[p];
        if (pe[i] < E_TOKN) {
            // + sum_h tw2[e][n][h] * (w*H)[d][h]
            gemm_accum<HNN>(acc,
                g_tw2f + (size_t)pe[i] * NN * HNN + (size_t)mT * HNN,
                g_hidf + (size_t)p * HID_ELEMS + (size_t)nT * HNN);
        } else {
            int ec = pe[i] - E_TOKN;
            // + sum_h (w*G)[n][h] * cw2[e][d][h]
            gemm_accum<HDD>(acc,
                g_hidf + (size_t)p * HID_ELEMS + (size_t)mT * HDD,
                g_cw2f + (size_t)ec * DD * HDD + (size_t)nT * HDD);
        }
    }

    // --- epilogue: weight-combined bias, write fp32 out[b][n][d] ---
    extern __shared__ __align__(128) unsigned char dsm[];
    const int tid = threadIdx.x, lane = tid & 31, wid = tid >> 5;
    const int wm = wid & 1, wn = wid >> 1;
    float* st = (float*)dsm + wid * 288;
    const int r  = lane >> 1;
    const int c0 = (lane & 1) * 8;
    float* outp = out + (size_t)b * NN * DD;

    #pragma unroll
    for (int mt = 0; mt < 4; mt++) {
        #pragma unroll
        for (int q = 0; q < 4; q++) {
            wmma::store_matrix_sync(st, acc[mt][q], 16, wmma::mem_row_major);
            __syncwarp();
            int row = mT + wm * 64 + mt * 16 + r;
            int col = nT + wn * 64 + q * 16 + c0;
            float v[8];
            #pragma unroll
            for (int j = 0; j < 8; j++) v[j] = st[r * 16 + c0 + j];
            #pragma unroll
            for (int i = 0; i < 2; i++) {
                if (pe[i] < E_TOKN) {
                    float bb = pw[i] * __ldg(&tb2[pe[i] * NN + row]);
                    #pragma unroll
                    for (int j = 0; j < 8; j++) v[j] += bb;
                } else {
                    int ec = pe[i] - E_TOKN;
                    #pragma unroll
                    for (int j = 0; j < 8; j++)
                        v[j] += pw[i] * __ldg(&cb2[ec * DD + col + j]);
                }
            }
            *(float4*)(outp + (size_t)row * DD + col)     = *(float4*)&v[0];
            *(float4*)(outp + (size_t)row * DD + col + 4) = *(float4*)&v[4];
            __syncwarp();
        }
    }
}

// ---------------------------------------------------------------------------
// Launch — only harness pointers cross host->device. ncu capture lands on
// launch index 3 = k_l1.
// ---------------------------------------------------------------------------
extern "C" void kernel_launch(void* const* d_in, const int* in_sizes, int n_in,
                              void* d_out, int out_size) {
    const float* x        = (const float*)d_in[0];
    const float* router_w = (const float*)d_in[1];
    const float* tok_w1   = (const float*)d_in[2];
    const float* tok_b1   = (const float*)d_in[3];
    const float* tok_w2   = (const float*)d_in[4];
    const float* tok_b2   = (const float*)d_in[5];
    const float* ch_w1    = (const float*)d_in[6];
    const float* ch_b1    = (const float*)d_in[7];
    const float* ch_w2    = (const float*)d_in[8];
    const float* ch_b2    = (const float*)d_in[9];
    float* out = (float*)d_out;

    long long bnd = (long long)BB * NN * DD;
    int has_aux = (long long)out_size > bnd;

    cudaFuncSetAttribute(k_l1,    cudaFuncAttributeMaxDynamicSharedMemorySize, SMEM_TOT);
    cudaFuncSetAttribute(k_l2out, cudaFuncAttributeMaxDynamicSharedMemorySize, SMEM_TOT);

    // 0: mean, 1: router, 2: fused conversions
    k_mean<<<(BB * DD + 255) / 256, 256>>>(x);
    k_router<<<1, 256>>>(router_w, out, bnd, has_aux);
    k_convert<<<NB_TOTAL, 256>>>(x, tok_w1, tok_w2, ch_w1, ch_w2);

    // 3: merged L1 GEMM (writes weight-pre-scaled fp16 hidden)
    dim3 g_l1(192, 1, NPAIR);
    k_l1<<<g_l1, 128, SMEM_TOT>>>(tok_b1, ch_b1);

    // 4: fused L2 + combine (both pairs accumulate, writes out directly)
    dim3 g_l2o(48, 1, BB);
    k_l2out<<<g_l2o, 128, SMEM_TOT>>>(tok_b2, ch_b2, out);
}

// round 14
// speedup vs baseline: 1.1889x; 1.0843x over previous
#include <cuda_runtime.h>
#include <cuda_fp16.h>
#include <mma.h>
#include <math.h>
#include <stdint.h>

using namespace nvcuda;

// ---------------------------------------------------------------------------
// Problem constants
// ---------------------------------------------------------------------------
#define BB 32
#define NN 1024
#define DD 768
#define E_TOKN 4
#define E_CHN 4
#define EE 8
#define TOPK 2
#define HNN 4096
#define HDD 3072
#define NPAIR (BB * TOPK)            // 64 selected (batch, expert) pairs
#define HID_ELEMS (DD * HNN)         // 3145728 == NN*HDD
#define CON_ELEMS (NN * DD)          // 786432

// ---------------------------------------------------------------------------
// Static device scratch (uint4-typed: guaranteed 16B alignment).
// RULE (rounds 3-5 root cause): device-global addresses are formed ONLY in
// device code — host-side g_* is the shadow symbol (ATS makes it writable!).
// ---------------------------------------------------------------------------
__device__ float g_xm[BB * DD];
__device__ int   g_pair_e[NPAIR];
__device__ float g_pair_w[NPAIR];

__device__ uint4 g_xf_raw  [BB * NN * DD / 8];          // x fp16 [b][n][d]
__device__ uint4 g_xtf_raw [BB * DD * NN / 8];          // x^T fp16 [b][d][n]
__device__ uint4 g_tw1f_raw[E_TOKN * HNN * NN / 8];
__device__ uint4 g_tw2f_raw[E_TOKN * NN * HNN / 8];
__device__ uint4 g_cw1f_raw[E_CHN * HDD * DD / 8];
__device__ uint4 g_cw2f_raw[E_CHN * DD * HDD / 8];
__device__ uint4 g_hidf_raw[(size_t)NPAIR * HID_ELEMS / 8];   // ~402 MB fp16

#define g_xf   ((__half*)g_xf_raw)
#define g_xtf  ((__half*)g_xtf_raw)
#define g_tw1f ((__half*)g_tw1f_raw)
#define g_tw2f ((__half*)g_tw2f_raw)
#define g_cw1f ((__half*)g_cw1f_raw)
#define g_cw2f ((__half*)g_cw2f_raw)
#define g_hidf ((__half*)g_hidf_raw)

// ---------------------------------------------------------------------------
// Helpers
// ---------------------------------------------------------------------------
// 2-wide gelu using tanh.approx.f16x2, scaled by per-pair weight.
__device__ __forceinline__ __half2 gelu2_h_scaled(float a, float b, __half2 ws) {
    const float c = 0.7978845608028654f;
    float ua = c * (a + 0.044715f * a * a * a);
    float ub = c * (b + 0.044715f * b * b * b);
    __half2 u2 = __floats2half2_rn(ua, ub);
    uint32_t uu = *reinterpret_cast<uint32_t*>(&u2);
    uint32_t tt;
    asm("tanh.approx.f16x2 %0, %1;" : "=r"(tt) : "r"(uu));
    __half2 t2 = *reinterpret_cast<__half2*>(&tt);
    __half2 vh = __floats2half2_rn(a, b);
    __half2 one  = __float2half2_rn(1.0f);
    __half2 half_ = __float2half2_rn(0.5f);
    __half2 g = __hmul2(__hmul2(half_, vh), __hadd2(one, t2));
    return __hmul2(g, ws);
}

__device__ __forceinline__ uint32_t smem_u32(const void* p) {
    uint32_t a;
    asm("{ .reg .u64 t; cvta.to.shared.u64 t, %1; cvt.u32.u64 %0, t; }"
        : "=r"(a) : "l"(p));
    return a;
}

#define CP_ASYNC16(dst32, src) \
    asm volatile("cp.async.cg.shared.global [%0], [%1], 16;" \
                 :: "r"(dst32), "l"(src) : "memory")
#define CP_COMMIT()  asm volatile("cp.async.commit_group;" ::: "memory")
#define CP_WAIT0()   asm volatile("cp.async.wait_group 0;" ::: "memory")

// ---------------------------------------------------------------------------
// Kernel: xm[b,d] = mean_n x[b,n,d]
// ---------------------------------------------------------------------------
__global__ void k_mean(const float* __restrict__ x) {
    int idx = blockIdx.x * blockDim.x + threadIdx.x;
    if (idx >= BB * DD) return;
    int b = idx / DD;
    int d = idx - b * DD;
    const float* p = x + (size_t)b * NN * DD + d;
    float s = 0.0f;
    #pragma unroll 8
    for (int n = 0; n < NN; n++) s += p[(size_t)n * DD];
    g_xm[idx] = s * (1.0f / (float)NN);
}

// ---------------------------------------------------------------------------
// Kernel: router logits, softmax, top-2, aux loss. Single block, 256 thr.
// ---------------------------------------------------------------------------
__global__ void k_router(const float* __restrict__ rw, float* __restrict__ out,
                         long long aux_idx, int has_aux) {
    __shared__ float probs[BB][EE];
    __shared__ int   top1s[BB];
    __shared__ float partial[EE];
    int t = threadIdx.x;

    {
        int b = t >> 3, e = t & 7;
        const float* xm = g_xm + b * DD;
        const float* w  = rw + e * DD;
        float s = 0.0f;
        #pragma unroll 8
        for (int d = 0; d < DD; d++) s += xm[d] * w[d];
        probs[b][e] = s;
    }
    __syncthreads();

    if (t < BB) {
        float l[EE];
        float mx = -1e30f;
        #pragma unroll
        for (int e = 0; e < EE; e++) { l[e] = probs[t][e]; mx = fmaxf(mx, l[e]); }
        float sum = 0.0f;
        #pragma unroll
        for (int e = 0; e < EE; e++) { l[e] = expf(l[e] - mx); sum += l[e]; }
        float inv = 1.0f / sum;
        #pragma unroll
        for (int e = 0; e < EE; e++) { l[e] *= inv; probs[t][e] = l[e]; }
        int i0 = 0; float v0 = l[0];
        #pragma unroll
        for (int e = 1; e < EE; e++) if (l[e] > v0) { v0 = l[e]; i0 = e; }
        int i1 = -1; float v1 = -1e30f;
        #pragma unroll
        for (int e = 0; e < EE; e++) if (e != i0 && l[e] > v1) { v1 = l[e]; i1 = e; }
        float inv01 = 1.0f / (v0 + v1);
        g_pair_e[2 * t]     = i0; g_pair_w[2 * t]     = v0 * inv01;
        g_pair_e[2 * t + 1] = i1; g_pair_w[2 * t + 1] = v1 * inv01;
        top1s[t] = i0;
    }
    __syncthreads();

    if (t < EE) {
        float ps = 0.0f; int c = 0;
        for (int b = 0; b < BB; b++) { ps += probs[b][t]; c += (top1s[b] == t); }
        partial[t] = ps * (float)c;
    }
    __syncthreads();

    if (t == 0 && has_aux) {
        float s = 0.0f;
        #pragma unroll
        for (int e = 0; e < EE; e++) s += partial[e];
        out[aux_idx] = s * ((float)EE / ((float)BB * (float)BB));
    }
}

// ---------------------------------------------------------------------------
// Fused conversion kernel: all fp32 -> fp16 conversions + x transpose.
// ---------------------------------------------------------------------------
#define NB_X   24576
#define NB_XT  24576
#define NB_TW1 16384
#define NB_TW2 16384
#define NB_CW1 9216
#define NB_CW2 9216
#define NB_TOTAL (NB_X + NB_XT + NB_TW1 + NB_TW2 + NB_CW1 + NB_CW2)

__device__ __forceinline__ void cvt4(const float* __restrict__ s, __half* d, int i) {
    float4 v = ((const float4*)s)[i];
    __half2 a = __floats2half2_rn(v.x, v.y);
    __half2 b = __floats2half2_rn(v.z, v.w);
    uint2 u;
    u.x = *reinterpret_cast<uint32_t*>(&a);
    u.y = *reinterpret_cast<uint32_t*>(&b);
    ((uint2*)d)[i] = u;
}

__global__ void k_convert(const float* __restrict__ x,
                          const float* __restrict__ tw1,
                          const float* __restrict__ tw2,
                          const float* __restrict__ cw1,
                          const float* __restrict__ cw2) {
    __shared__ float t[32][33];
    int bid = blockIdx.x;
    int tid = threadIdx.x;

    if (bid < NB_X) {
        cvt4(x, g_xf, bid * 256 + tid);
    } else if (bid < NB_X + NB_XT) {
        int r = bid - NB_X;
        int b = r / 768;
        int rem = r - b * 768;
        int nblk = rem / 24;
        int dblk = rem - nblk * 24;
        int d0 = dblk * 32, n0 = nblk * 32;
        int tx = tid & 31, ty = tid >> 5;
        #pragma unroll
        for (int i = 0; i < 4; i++) {
            int n = n0 + ty + i * 8;
            t[ty + i * 8][tx] = x[((size_t)b * NN + n) * DD + d0 + tx];
        }
        __syncthreads();
        #pragma unroll
        for (int i = 0; i < 4; i++) {
            int d = d0 + ty + i * 8;
            g_xtf[((size_t)b * DD + d) * NN + n0 + tx] =
                __float2half_rn(t[tx][ty + i * 8]);
        }
    } else if (bid < NB_X + NB_XT + NB_TW1) {
        cvt4(tw1, g_tw1f, (bid - NB_X - NB_XT) * 256 + tid);
    } else if (bid < NB_X + NB_XT + NB_TW1 + NB_TW2) {
        cvt4(tw2, g_tw2f, (bid - NB_X - NB_XT - NB_TW1) * 256 + tid);
    } else if (bid < NB_X + NB_XT + NB_TW1 + NB_TW2 + NB_CW1) {
        cvt4(cw1, g_cw1f, (bid - NB_X - NB_XT - NB_TW1 - NB_TW2) * 256 + tid);
    } else {
        cvt4(cw2, g_cw2f, (bid - NB_X - NB_XT - NB_TW1 - NB_TW2 - NB_CW1) * 256 + tid);
    }
}

// ---------------------------------------------------------------------------
// GEMM accumulation core: adds A(128xK) * B(128xK)^T into acc.
// CTA 128x128, 128 threads = 4 warps (2x2), warp tile 64x64, BK=64,
// cp.async 2-stage, SINGLE __syncthreads per chunk (CUTLASS-multistage
// ordering: wait -> sync -> compute ks0 -> prefetch -> compute ks1..3).
// The sync at chunk top proves all warps finished reading the prefetch
// target (read during chunk-1), so the trailing barrier is gone and the
// cp.async issue burst hides under the MMAs.
// ---------------------------------------------------------------------------
#define BK 64
#define RSTR 144                      // bytes per smem row
#define STRDH 72                      // halves per smem row
#define A_TILE_B (128 * RSTR)         // 18432
#define STAGE_B (2 * A_TILE_B)        // 36864
#define SMEM_TOT (2 * STAGE_B)        // 73728

template<int K>
__device__ __forceinline__ void gemm_accum(
        wmma::fragment<wmma::accumulator, 16, 16, 16, float> (&acc)[4][4],
        const __half* pA, const __half* pB) {
    extern __shared__ __align__(128) unsigned char dsm[];
    const uint32_t sbase = smem_u32(dsm);
    const int tid = threadIdx.x, wid = tid >> 5;
    const int wm = wid & 1, wn = wid >> 1;    // 2 x 2 warp grid, 64x64 tiles

    auto load_stage = [&](int stage, int chk) {
        uint32_t sb = sbase + stage * STAGE_B;
        #pragma unroll
        for (int it = 0; it < 8; it++) {           // A
            int idx = it * 128 + tid;
            int row = idx >> 3, c = idx & 7;
            CP_ASYNC16(sb + row * RSTR + c * 16,
                       pA + (size_t)row * K + chk * BK + c * 8);
        }
        #pragma unroll
        for (int it = 0; it < 8; it++) {           // B
            int idx = it * 128 + tid;
            int row = idx >> 3, c = idx & 7;
            CP_ASYNC16(sb + A_TILE_B + row * RSTR + c * 16,
                       pB + (size_t)row * K + chk * BK + c * 8);
        }
        CP_COMMIT();
    };

    const int NCH = K / BK;
    load_stage(0, 0);

    for (int chk = 0; chk < NCH; chk++) {
        CP_WAIT0();          // stage chk data arrived (single group in flight)
        __syncthreads();     // visible to all; all warps done reading stage chk^1

        __half* sA = (__half*)(dsm + (chk & 1) * STAGE_B);
        __half* sB = (__half*)(dsm + (chk & 1) * STAGE_B + A_TILE_B);

        #pragma unroll
        for (int ks = 0; ks < BK / 16; ks++) {
            wmma::fragment<wmma::matrix_a, 16, 16, 16, __half, wmma::row_major> af[4];
            wmma::fragment<wmma::matrix_b, 16, 16, 16, __half, wmma::col_major> bf[4];
            #pragma unroll
            for (int mt = 0; mt < 4; mt++)
                wmma::load_matrix_sync(af[mt], &sA[(wm * 64 + mt * 16) * STRDH + ks * 16], STRDH);
            #pragma unroll
            for (int p = 0; p < 4; p++)
                wmma::load_matrix_sync(bf[p], &sB[(wn * 64 + p * 16) * STRDH + ks * 16], STRDH);
            #pragma unroll
            for (int mt = 0; mt < 4; mt++)
                #pragma unroll
                for (int p = 0; p < 4; p++)
                    wmma::mma_sync(acc[mt][p], af[mt], bf[p], acc[mt][p]);
            // Prefetch next chunk after the first ks block: issue cost hides
            // under the remaining MMAs; target buffer is safe post-sync.
            if (ks == 0 && chk + 1 < NCH)
                load_stage((chk + 1) & 1, chk + 1);
        }
    }
}

// ---------------------------------------------------------------------------
// Merged L1 kernel: token + channel first layers; hidden written as fp16
// PRE-SCALED by the pair's routing weight (enables fused L2+combine).
// grid (192, 1, NPAIR): token 6(m) x 32(n) tiles; channel 8 x 24.
// ---------------------------------------------------------------------------
__global__ void __launch_bounds__(128, 3)
k_l1(const float* __restrict__ tb1, const float* __restrict__ cb1) {
    int p = blockIdx.z;
    int e = g_pair_e[p];
    int b = p >> 1;
    int bx = blockIdx.x;
    float w = g_pair_w[p];

    wmma::fragment<wmma::accumulator, 16, 16, 16, float> acc[4][4];
    #pragma unroll
    for (int mt = 0; mt < 4; mt++)
        #pragma unroll
        for (int q = 0; q < 4; q++) wmma::fill_fragment(acc[mt][q], 0.0f);

    int mT, nT, Nn;
    const float* bias;
    if (e < E_TOKN) {
        // H[p][d][h] = w * gelu( sum_n xT[b][d][n] * tw1[e][h][n] + b1[e][h] )
        mT = (bx % 6) * 128; nT = (bx / 6) * 128; Nn = HNN;
        bias = tb1 + e * HNN;
        gemm_accum<NN>(acc,
            g_xtf + (size_t)b * DD * NN + (size_t)mT * NN,
            g_tw1f + (size_t)e * HNN * NN + (size_t)nT * NN);
    } else {
        int ec = e - E_TOKN;
        // G[p][n][h] = w * gelu( sum_d x[b][n][d] * cw1[e][h][d] + b1[e][h] )
        mT = (bx % 8) * 128; nT = (bx / 8) * 128; Nn = HDD;
        bias = cb1 + ec * HDD;
        gemm_accum<DD>(acc,
            g_xf + (size_t)b * NN * DD + (size_t)mT * DD,
            g_cw1f + (size_t)ec * HDD * DD + (size_t)nT * DD);
    }

    // --- epilogue: bias + gelu(f16x2 tanh) + weight scale -> fp16 hidden ---
    // Staging lives in stage-0 bytes [0, 4608): disjoint from stage-1 reads
    // of any warp still finishing the (always odd-indexed) last chunk.
    extern __shared__ __align__(128) unsigned char dsm[];
    const int tid = threadIdx.x, lane = tid & 31, wid = tid >> 5;
    const int wm = wid & 1, wn = wid >> 1;
    float* st = (float*)dsm + wid * 288;
    const int r  = lane >> 1;
    const int c0 = (lane & 1) * 8;
    __half2 ws = __float2half2_rn(w);
    __half* Ch = g_hidf + (size_t)p * HID_ELEMS;

    #pragma unroll
    for (int mt = 0; mt < 4; mt++) {
        #pragma unroll
        for (int q = 0; q < 4; q++) {
            wmma::store_matrix_sync(st, acc[mt][q], 16, wmma::mem_row_major);
            __syncwarp();
            int row = mT + wm * 64 + mt * 16 + r;
            int col = nT + wn * 64 + q * 16 + c0;
            float v[8];
            #pragma unroll
            for (int j = 0; j < 8; j++)
                v[j] = st[r * 16 + c0 + j] + __ldg(&bias[col + j]);
            __half2 hv[4];
            #pragma unroll
            for (int j = 0; j < 4; j++)
                hv[j] = gelu2_h_scaled(v[2 * j], v[2 * j + 1], ws);
            *(uint4*)(Ch + (size_t)row * Nn + col) = *(uint4*)hv;
            __syncwarp();
        }
    }
}

// ---------------------------------------------------------------------------
// Fused L2 + combine kernel: per batch b, BOTH selected pairs accumulate
// sequentially into one accumulator (hidden is pre-scaled by w), then the
// weight-combined bias is added and the result written straight to out.
// grid (48, 1, BB); tiles M=NN(8) x N=DD(6). Deterministic (no atomics).
// ---------------------------------------------------------------------------
__global__ void __launch_bounds__(128, 3)
k_l2out(const float* __restrict__ tb2, const float* __restrict__ cb2,
        float* __restrict__ out) {
    int b  = blockIdx.z;
    int bx = blockIdx.x;
    int mT = (bx % 8) * 128, nT = (bx / 8) * 128;

    wmma::fragment<wmma::accumulator, 16, 16, 16, float> acc[4][4];
    #pragma unroll
    for (int mt = 0; mt < 4; mt++)
        #pragma unroll
        for (int q = 0; q < 4; q++) wmma::fill_fragment(acc[mt][q], 0.0f);

    int   pe[2];
    float pw[2];
    #pragma unroll
    for (int i = 0; i < 2; i++) {
        int p = 2 * b + i;
        pe[i] = g_pair_e[p];
        pw[i] = g_pair_w[p];
        if (pe[i] < E_TOKN) {
            // + sum_h tw2[e][n][h] * (w*H)[d][h]
            gemm_accum<HNN>(acc,
                g_tw2f + (size_t)pe[i] * NN * HNN + (size_t)mT * HNN,
                g_hidf + (size_t)p * HID_ELEMS + (size_t)nT * HNN);
        } else {
            int ec = pe[i] - E_TOKN;
            // + sum_h (w*G)[n][h] * cw2[e][d][h]
            gemm_accum<HDD>(acc,
                g_hidf + (size_t)p * HID_ELEMS + (size_t)mT * HDD,
                g_cw2f + (size_t)ec * DD * HDD + (size_t)nT * HDD);
        }
    }

    // --- epilogue: weight-combined bias, write fp32 out[b][n][d] ---
    extern __shared__ __align__(128) unsigned char dsm[];
    const int tid = threadIdx.x, lane = tid & 31, wid = tid >> 5;
    const int wm = wid & 1, wn = wid >> 1;
    float* st = (float*)dsm + wid * 288;
    const int r  = lane >> 1;
    const int c0 = (lane & 1) * 8;
    float* outp = out + (size_t)b * NN * DD;

    #pragma unroll
    for (int mt = 0; mt < 4; mt++) {
        #pragma unroll
        for (int q = 0; q < 4; q++) {
            wmma::store_matrix_sync(st, acc[mt][q], 16, wmma::mem_row_major);
            __syncwarp();
            int row = mT + wm * 64 + mt * 16 + r;
            int col = nT + wn * 64 + q * 16 + c0;
            float v[8];
            #pragma unroll
            for (int j = 0; j < 8; j++) v[j] = st[r * 16 + c0 + j];
            #pragma unroll
            for (int i = 0; i < 2; i++) {
                if (pe[i] < E_TOKN) {
                    float bb = pw[i] * __ldg(&tb2[pe[i] * NN + row]);
                    #pragma unroll
                    for (int j = 0; j < 8; j++) v[j] += bb;
                } else {
                    int ec = pe[i] - E_TOKN;
                    #pragma unroll
                    for (int j = 0; j < 8; j++)
                        v[j] += pw[i] * __ldg(&cb2[ec * DD + col + j]);
                }
            }
            *(float4*)(outp + (size_t)row * DD + col)     = *(float4*)&v[0];
            *(float4*)(outp + (size_t)row * DD + col + 4) = *(float4*)&v[4];
            __syncwarp();
        }
    }
}

// ---------------------------------------------------------------------------
// Launch — only harness pointers cross host->device. ncu capture lands on
// launch index 3 = k_l1.
// ---------------------------------------------------------------------------
extern "C" void kernel_launch(void* const* d_in, const int* in_sizes, int n_in,
                              void* d_out, int out_size) {
    const float* x        = (const float*)d_in[0];
    const float* router_w = (const float*)d_in[1];
    const float* tok_w1   = (const float*)d_in[2];
    const float* tok_b1   = (const float*)d_in[3];
    const float* tok_w2   = (const float*)d_in[4];
    const float* tok_b2   = (const float*)d_in[5];
    const float* ch_w1    = (const float*)d_in[6];
    const float* ch_b1    = (const float*)d_in[7];
    const float* ch_w2    = (const float*)d_in[8];
    const float* ch_b2    = (const float*)d_in[9];
    float* out = (float*)d_out;

    long long bnd = (long long)BB * NN * DD;
    int has_aux = (long long)out_size > bnd;

    cudaFuncSetAttribute(k_l1,    cudaFuncAttributeMaxDynamicSharedMemorySize, SMEM_TOT);
    cudaFuncSetAttribute(k_l2out, cudaFuncAttributeMaxDynamicSharedMemorySize, SMEM_TOT);

    // 0: mean, 1: router, 2: fused conversions
    k_mean<<<(BB * DD + 255) / 256, 256>>>(x);
    k_router<<<1, 256>>>(router_w, out, bnd, has_aux);
    k_convert<<<NB_TOTAL, 256>>>(x, tok_w1, tok_w2, ch_w1, ch_w2);

    // 3: merged L1 GEMM (writes weight-pre-scaled fp16 hidden)
    dim3 g_l1(192, 1, NPAIR);
    k_l1<<<g_l1, 128, SMEM_TOT>>>(tok_b1, ch_b1);

    // 4: fused L2 + combine (both pairs accumulate, writes out directly)
    dim3 g_l2o(48, 1, BB);
    k_l2out<<<g_l2o, 128, SMEM_TOT>>>(tok_b2, ch_b2, out);
}

// round 15
// speedup vs baseline: 1.2106x; 1.0182x over previous
#include <cuda_runtime.h>
#include <cuda_fp16.h>
#include <mma.h>
#include <math.h>
#include <stdint.h>

using namespace nvcuda;

// ---------------------------------------------------------------------------
// Problem constants
// ---------------------------------------------------------------------------
#define BB 32
#define NN 1024
#define DD 768
#define E_TOKN 4
#define E_CHN 4
#define EE 8
#define TOPK 2
#define HNN 4096
#define HDD 3072
#define NPAIR (BB * TOPK)            // 64 selected (batch, expert) pairs
#define HID_ELEMS (DD * HNN)         // 3145728 == NN*HDD

// ---------------------------------------------------------------------------
// Static device scratch (uint4-typed: guaranteed 16B alignment).
// RULE (rounds 3-5 root cause): device-global addresses are formed ONLY in
// device code — host-side g_* is the shadow symbol (ATS makes it writable!).
// ---------------------------------------------------------------------------
__device__ float g_xm[BB * DD];
__device__ int   g_pair_e[NPAIR];
__device__ float g_pair_w[NPAIR];

__device__ uint4 g_xf_raw  [BB * NN * DD / 8];          // x fp16 [b][n][d]
__device__ uint4 g_tw1f_raw[E_TOKN * HNN * NN / 8];
__device__ uint4 g_tw2f_raw[E_TOKN * NN * HNN / 8];
__device__ uint4 g_cw1f_raw[E_CHN * HDD * DD / 8];
__device__ uint4 g_cw2f_raw[E_CHN * DD * HDD / 8];
__device__ uint4 g_hidf_raw[(size_t)NPAIR * HID_ELEMS / 8];   // ~402 MB fp16

#define g_xf   ((__half*)g_xf_raw)
#define g_tw1f ((__half*)g_tw1f_raw)
#define g_tw2f ((__half*)g_tw2f_raw)
#define g_cw1f ((__half*)g_cw1f_raw)
#define g_cw2f ((__half*)g_cw2f_raw)
#define g_hidf ((__half*)g_hidf_raw)

// ---------------------------------------------------------------------------
// Helpers
// ---------------------------------------------------------------------------
// 2-wide gelu using tanh.approx.f16x2, scaled by per-pair weight.
__device__ __forceinline__ __half2 gelu2_h_scaled(float a, float b, __half2 ws) {
    const float c = 0.7978845608028654f;
    float ua = c * (a + 0.044715f * a * a * a);
    float ub = c * (b + 0.044715f * b * b * b);
    __half2 u2 = __floats2half2_rn(ua, ub);
    uint32_t uu = *reinterpret_cast<uint32_t*>(&u2);
    uint32_t tt;
    asm("tanh.approx.f16x2 %0, %1;" : "=r"(tt) : "r"(uu));
    __half2 t2 = *reinterpret_cast<__half2*>(&tt);
    __half2 vh = __floats2half2_rn(a, b);
    __half2 one  = __float2half2_rn(1.0f);
    __half2 half_ = __float2half2_rn(0.5f);
    __half2 g = __hmul2(__hmul2(half_, vh), __hadd2(one, t2));
    return __hmul2(g, ws);
}

__device__ __forceinline__ uint32_t smem_u32(const void* p) {
    uint32_t a;
    asm("{ .reg .u64 t; cvta.to.shared.u64 t, %1; cvt.u32.u64 %0, t; }"
        : "=r"(a) : "l"(p));
    return a;
}

#define CP_ASYNC16(dst32, src) \
    asm volatile("cp.async.cg.shared.global [%0], [%1], 16;" \
                 :: "r"(dst32), "l"(src) : "memory")
#define CP_COMMIT()  asm volatile("cp.async.commit_group;" ::: "memory")
#define CP_WAIT0()   asm volatile("cp.async.wait_group 0;" ::: "memory")

// ---------------------------------------------------------------------------
// Kernel: xm[b,d] = mean_n x[b,n,d]
// ---------------------------------------------------------------------------
__global__ void k_mean(const float* __restrict__ x) {
    int idx = blockIdx.x * blockDim.x + threadIdx.x;
    if (idx >= BB * DD) return;
    int b = idx / DD;
    int d = idx - b * DD;
    const float* p = x + (size_t)b * NN * DD + d;
    float s = 0.0f;
    #pragma unroll 8
    for (int n = 0; n < NN; n++) s += p[(size_t)n * DD];
    g_xm[idx] = s * (1.0f / (float)NN);
}

// ---------------------------------------------------------------------------
// Kernel: router logits, softmax, top-2, aux loss. Single block, 256 thr.
// ---------------------------------------------------------------------------
__global__ void k_router(const float* __restrict__ rw, float* __restrict__ out,
                         long long aux_idx, int has_aux) {
    __shared__ float probs[BB][EE];
    __shared__ int   top1s[BB];
    __shared__ float partial[EE];
    int t = threadIdx.x;

    {
        int b = t >> 3, e = t & 7;
        const float* xm = g_xm + b * DD;
        const float* w  = rw + e * DD;
        float s = 0.0f;
        #pragma unroll 8
        for (int d = 0; d < DD; d++) s += xm[d] * w[d];
        probs[b][e] = s;
    }
    __syncthreads();

    if (t < BB) {
        float l[EE];
        float mx = -1e30f;
        #pragma unroll
        for (int e = 0; e < EE; e++) { l[e] = probs[t][e]; mx = fmaxf(mx, l[e]); }
        float sum = 0.0f;
        #pragma unroll
        for (int e = 0; e < EE; e++) { l[e] = expf(l[e] - mx); sum += l[e]; }
        float inv = 1.0f / sum;
        #pragma unroll
        for (int e = 0; e < EE; e++) { l[e] *= inv; probs[t][e] = l[e]; }
        int i0 = 0; float v0 = l[0];
        #pragma unroll
        for (int e = 1; e < EE; e++) if (l[e] > v0) { v0 = l[e]; i0 = e; }
        int i1 = -1; float v1 = -1e30f;
        #pragma unroll
        for (int e = 0; e < EE; e++) if (e != i0 && l[e] > v1) { v1 = l[e]; i1 = e; }
        float inv01 = 1.0f / (v0 + v1);
        g_pair_e[2 * t]     = i0; g_pair_w[2 * t]     = v0 * inv01;
        g_pair_e[2 * t + 1] = i1; g_pair_w[2 * t + 1] = v1 * inv01;
        top1s[t] = i0;
    }
    __syncthreads();

    if (t < EE) {
        float ps = 0.0f; int c = 0;
        for (int b = 0; b < BB; b++) { ps += probs[b][t]; c += (top1s[b] == t); }
        partial[t] = ps * (float)c;
    }
    __syncthreads();

    if (t == 0 && has_aux) {
        float s = 0.0f;
        #pragma unroll
        for (int e = 0; e < EE; e++) s += partial[e];
        out[aux_idx] = s * ((float)EE / ((float)BB * (float)BB));
    }
}

// ---------------------------------------------------------------------------
// Fused conversion kernel: all fp32 -> fp16 conversions (no transpose —
// token L1 now consumes x directly via col-major A fragments).
// ---------------------------------------------------------------------------
#define NB_X   24576
#define NB_TW1 16384
#define NB_TW2 16384
#define NB_CW1 9216
#define NB_CW2 9216
#define NB_TOTAL (NB_X + NB_TW1 + NB_TW2 + NB_CW1 + NB_CW2)

__device__ __forceinline__ void cvt4(const float* __restrict__ s, __half* d, int i) {
    float4 v = ((const float4*)s)[i];
    __half2 a = __floats2half2_rn(v.x, v.y);
    __half2 b = __floats2half2_rn(v.z, v.w);
    uint2 u;
    u.x = *reinterpret_cast<uint32_t*>(&a);
    u.y = *reinterpret_cast<uint32_t*>(&b);
    ((uint2*)d)[i] = u;
}

__global__ void k_convert(const float* __restrict__ x,
                          const float* __restrict__ tw1,
                          const float* __restrict__ tw2,
                          const float* __restrict__ cw1,
                          const float* __restrict__ cw2) {
    int bid = blockIdx.x;
    int tid = threadIdx.x;

    if (bid < NB_X) {
        cvt4(x, g_xf, bid * 256 + tid);
    } else if (bid < NB_X + NB_TW1) {
        cvt4(tw1, g_tw1f, (bid - NB_X) * 256 + tid);
    } else if (bid < NB_X + NB_TW1 + NB_TW2) {
        cvt4(tw2, g_tw2f, (bid - NB_X - NB_TW1) * 256 + tid);
    } else if (bid < NB_X + NB_TW1 + NB_TW2 + NB_CW1) {
        cvt4(cw1, g_cw1f, (bid - NB_X - NB_TW1 - NB_TW2) * 256 + tid);
    } else {
        cvt4(cw2, g_cw2f, (bid - NB_X - NB_TW1 - NB_TW2 - NB_CW1) * 256 + tid);
    }
}

// ---------------------------------------------------------------------------
// GEMM accumulation core: adds A(128xK) * B(128xK)^T into acc.
// CTA 128x128, 128 threads = 4 warps (2x2), warp tile 64x64, BK=64,
// cp.async 2-stage, single __syncthreads per chunk, prefetch hidden
// under MMAs (round-14 proven ordering).
// ACOLLD == 0 : A row-major [128 m][K], k-contiguous (smem 144B rows).
// ACOLLD  > 0 : A col-major in GMEM with leading dim ACOLLD (token L1:
//               A[m=d][k=n] = x[n][d]); smem tile = 64 k-rows x 128 m-halves
//               (272B rows; banks +4/row -> conflict-free), fragments loaded
//               wmma col_major with ldm=136.
// ---------------------------------------------------------------------------
#define BK 64
#define RSTR 144                      // bytes per smem row (row-major tiles)
#define STRDH 72                      // halves per row (row-major tiles)
#define CRSTR 272                     // bytes per smem row (col-major A tile)
#define CSTRDH 136                    // halves per row (col-major A tile)
#define A_TILE_B (128 * RSTR)         // 18432 (>= 64*272 = 17408)
#define STAGE_B (2 * A_TILE_B)        // 36864
#define SMEM_TOT (2 * STAGE_B)        // 73728

template<int K, int ACOLLD>
__device__ __forceinline__ void gemm_accum(
        wmma::fragment<wmma::accumulator, 16, 16, 16, float> (&acc)[4][4],
        const __half* pA, const __half* pB) {
    extern __shared__ __align__(128) unsigned char dsm[];
    const uint32_t sbase = smem_u32(dsm);
    const int tid = threadIdx.x, wid = tid >> 5;
    const int wm = wid & 1, wn = wid >> 1;    // 2 x 2 warp grid, 64x64 tiles

    auto load_stage = [&](int stage, int chk) {
        uint32_t sb = sbase + stage * STAGE_B;
        if (ACOLLD > 0) {
            // A: 64 k-rows x 256B (128 m-halves) = 1024 16B chunks
            #pragma unroll
            for (int it = 0; it < 8; it++) {
                int idx = it * 128 + tid;
                int row = idx >> 4, c = idx & 15;
                CP_ASYNC16(sb + row * CRSTR + c * 16,
                           pA + (size_t)(chk * BK + row) * ACOLLD + c * 8);
            }
        } else {
            // A: 128 m-rows x 128B (64 k-halves) = 1024 16B chunks
            #pragma unroll
            for (int it = 0; it < 8; it++) {
                int idx = it * 128 + tid;
                int row = idx >> 3, c = idx & 7;
                CP_ASYNC16(sb + row * RSTR + c * 16,
                           pA + (size_t)row * K + chk * BK + c * 8);
            }
        }
        #pragma unroll
        for (int it = 0; it < 8; it++) {           // B
            int idx = it * 128 + tid;
            int row = idx >> 3, c = idx & 7;
            CP_ASYNC16(sb + A_TILE_B + row * RSTR + c * 16,
                       pB + (size_t)row * K + chk * BK + c * 8);
        }
        CP_COMMIT();
    };

    const int NCH = K / BK;
    load_stage(0, 0);

    for (int chk = 0; chk < NCH; chk++) {
        CP_WAIT0();
        __syncthreads();

        __half* sA = (__half*)(dsm + (chk & 1) * STAGE_B);
        __half* sB = (__half*)(dsm + (chk & 1) * STAGE_B + A_TILE_B);

        #pragma unroll
        for (int ks = 0; ks < BK / 16; ks++) {
            wmma::fragment<wmma::matrix_b, 16, 16, 16, __half, wmma::col_major> bf[4];
            #pragma unroll
            for (int p = 0; p < 4; p++)
                wmma::load_matrix_sync(bf[p], &sB[(wn * 64 + p * 16) * STRDH + ks * 16], STRDH);

            if (ACOLLD > 0) {
                wmma::fragment<wmma::matrix_a, 16, 16, 16, __half, wmma::col_major> af[4];
                #pragma unroll
                for (int mt = 0; mt < 4; mt++)
                    wmma::load_matrix_sync(af[mt],
                        &sA[(ks * 16) * CSTRDH + wm * 64 + mt * 16], CSTRDH);
                #pragma unroll
                for (int mt = 0; mt < 4; mt++)
                    #pragma unroll
                    for (int p = 0; p < 4; p++)
                        wmma::mma_sync(acc[mt][p], af[mt], bf[p], acc[mt][p]);
            } else {
                wmma::fragment<wmma::matrix_a, 16, 16, 16, __half, wmma::row_major> af[4];
                #pragma unroll
                for (int mt = 0; mt < 4; mt++)
                    wmma::load_matrix_sync(af[mt],
                        &sA[(wm * 64 + mt * 16) * STRDH + ks * 16], STRDH);
                #pragma unroll
                for (int mt = 0; mt < 4; mt++)
                    #pragma unroll
                    for (int p = 0; p < 4; p++)
                        wmma::mma_sync(acc[mt][p], af[mt], bf[p], acc[mt][p]);
            }
            // Prefetch next chunk after first ks block; hides under MMAs.
            if (ks == 0 && chk + 1 < NCH)
                load_stage((chk + 1) & 1, chk + 1);
        }
    }
}

// ---------------------------------------------------------------------------
// Merged L1 kernel: token + channel first layers; hidden written as fp16
// PRE-SCALED by the pair's routing weight.
// grid (192, 1, NPAIR): token 6(m) x 32(n) tiles; channel 8 x 24.
// ---------------------------------------------------------------------------
__global__ void __launch_bounds__(128, 3)
k_l1(const float* __restrict__ tb1, const float* __restrict__ cb1) {
    int p = blockIdx.z;
    int e = g_pair_e[p];
    int b = p >> 1;
    int bx = blockIdx.x;
    float w = g_pair_w[p];

    wmma::fragment<wmma::accumulator, 16, 16, 16, float> acc[4][4];
    #pragma unroll
    for (int mt = 0; mt < 4; mt++)
        #pragma unroll
        for (int q = 0; q < 4; q++) wmma::fill_fragment(acc[mt][q], 0.0f);

    int mT, nT, Nn;
    const float* bias;
    if (e < E_TOKN) {
        // H[p][d][h] = w*gelu( sum_n x[b][n][d] * tw1[e][h][n] + b1[e][h] )
        // A = x[b] read col-major (A[m=d][k=n] = x[n][d], ld = DD)
        mT = (bx % 6) * 128; nT = (bx / 6) * 128; Nn = HNN;
        bias = tb1 + e * HNN;
        gemm_accum<NN, DD>(acc,
            g_xf + (size_t)b * NN * DD + mT,
            g_tw1f + (size_t)e * HNN * NN + (size_t)nT * NN);
    } else {
        int ec = e - E_TOKN;
        // G[p][n][h] = w*gelu( sum_d x[b][n][d] * cw1[e][h][d] + b1[e][h] )
        mT = (bx % 8) * 128; nT = (bx / 8) * 128; Nn = HDD;
        bias = cb1 + ec * HDD;
        gemm_accum<DD, 0>(acc,
            g_xf + (size_t)b * NN * DD + (size_t)mT * DD,
            g_cw1f + (size_t)ec * HDD * DD + (size_t)nT * DD);
    }

    // --- epilogue: bias + gelu(f16x2 tanh) + weight scale -> fp16 hidden ---
    extern __shared__ __align__(128) unsigned char dsm[];
    const int tid = threadIdx.x, lane = tid & 31, wid = tid >> 5;
    const int wm = wid & 1, wn = wid >> 1;
    float* st = (float*)dsm + wid * 288;
    const int r  = lane >> 1;
    const int c0 = (lane & 1) * 8;
    __half2 ws = __float2half2_rn(w);
    __half* Ch = g_hidf + (size_t)p * HID_ELEMS;

    #pragma unroll
    for (int mt = 0; mt < 4; mt++) {
        #pragma unroll
        for (int q = 0; q < 4; q++) {
            wmma::store_matrix_sync(st, acc[mt][q], 16, wmma::mem_row_major);
            __syncwarp();
            int row = mT + wm * 64 + mt * 16 + r;
            int col = nT + wn * 64 + q * 16 + c0;
            float v[8];
            #pragma unroll
            for (int j = 0; j < 8; j++)
                v[j] = st[r * 16 + c0 + j] + __ldg(&bias[col + j]);
            __half2 hv[4];
            #pragma unroll
            for (int j = 0; j < 4; j++)
                hv[j] = gelu2_h_scaled(v[2 * j], v[2 * j + 1], ws);
            *(uint4*)(Ch + (size_t)row * Nn + col) = *(uint4*)hv;
            __syncwarp();
        }
    }
}

// ---------------------------------------------------------------------------
// Fused L2 + combine kernel: per batch b, BOTH selected pairs accumulate
// sequentially into one accumulator (hidden is pre-scaled by w), then the
// weight-combined bias is added and the result written straight to out.
// grid (48, 1, BB); tiles M=NN(8) x N=DD(6). Deterministic (no atomics).
// ---------------------------------------------------------------------------
__global__ void __launch_bounds__(128, 3)
k_l2out(const float* __restrict__ tb2, const float* __restrict__ cb2,
        float* __restrict__ out) {
    int b  = blockIdx.z;
    int bx = blockIdx.x;
    int mT = (bx % 8) * 128, nT = (bx / 8) * 128;

    wmma::fragment<wmma::accumulator, 16, 16, 16, float> acc[4][4];
    #pragma unroll
    for (int mt = 0; mt < 4; mt++)
        #pragma unroll
        for (int q = 0; q < 4; q++) wmma::fill_fragment(acc[mt][q], 0.0f);

    int   pe[2];
    float pw[2];
    #pragma unroll
    for (int i = 0; i < 2; i++) {
        int p = 2 * b + i;
        pe[i] = g_pair_e[p];
        pw[i] = g_pair_w[p];
        if (pe[i] < E_TOKN) {
            gemm_accum<HNN, 0>(acc,
                g_tw2f + (size_t)pe[i] * NN * HNN + (size_t)mT * HNN,
                g_hidf + (size_t)p * HID_ELEMS + (size_t)nT * HNN);
        } else {
            int ec = pe[i] - E_TOKN;
            gemm_accum<HDD, 0>(acc,
                g_hidf + (size_t)p * HID_ELEMS + (size_t)mT * HDD,
                g_cw2f + (size_t)ec * DD * HDD + (size_t)nT * HDD);
        }
    }

    // --- epilogue: weight-combined bias, write fp32 out[b][n][d] ---
    extern __shared__ __align__(128) unsigned char dsm[];
    const int tid = threadIdx.x, lane = tid & 31, wid = tid >> 5;
    const int wm = wid & 1, wn = wid >> 1;
    float* st = (float*)dsm + wid * 288;
    const int r  = lane >> 1;
    const int c0 = (lane & 1) * 8;
    float* outp = out + (size_t)b * NN * DD;

    #pragma unroll
    for (int mt = 0; mt < 4; mt++) {
        #pragma unroll
        for (int q = 0; q < 4; q++) {
            wmma::store_matrix_sync(st, acc[mt][q], 16, wmma::mem_row_major);
            __syncwarp();
            int row = mT + wm * 64 + mt * 16 + r;
            int col = nT + wn * 64 + q * 16 + c0;
            float v[8];
            #pragma unroll
            for (int j = 0; j < 8; j++) v[j] = st[r * 16 + c0 + j];
            #pragma unroll
            for (int i = 0; i < 2; i++) {
                if (pe[i] < E_TOKN) {
                    float bb = pw[i] * __ldg(&tb2[pe[i] * NN + row]);
                    #pragma unroll
                    for (int j = 0; j < 8; j++) v[j] += bb;
                } else {
                    int ec = pe[i] - E_TOKN;
                    #pragma unroll
                    for (int j = 0; j < 8; j++)
                        v[j] += pw[i] * __ldg(&cb2[ec * DD + col + j]);
                }
            }
            *(float4*)(outp + (size_t)row * DD + col)     = *(float4*)&v[0];
            *(float4*)(outp + (size_t)row * DD + col + 4) = *(float4*)&v[4];
            __syncwarp();
        }
    }
}

// ---------------------------------------------------------------------------
// Launch — only harness pointers cross host->device. ncu capture lands on
// launch index 3 = k_l1.
// ---------------------------------------------------------------------------
extern "C" void kernel_launch(void* const* d_in, const int* in_sizes, int n_in,
                              void* d_out, int out_size) {
    const float* x        = (const float*)d_in[0];
    const float* router_w = (const float*)d_in[1];
    const float* tok_w1   = (const float*)d_in[2];
    const float* tok_b1   = (const float*)d_in[3];
    const float* tok_w2   = (const float*)d_in[4];
    const float* tok_b2   = (const float*)d_in[5];
    const float* ch_w1    = (const float*)d_in[6];
    const float* ch_b1    = (const float*)d_in[7];
    const float* ch_w2    = (const float*)d_in[8];
    const float* ch_b2    = (const float*)d_in[9];
    float* out = (float*)d_out;

    long long bnd = (long long)BB * NN * DD;
    int has_aux = (long long)out_size > bnd;

    cudaFuncSetAttribute(k_l1,    cudaFuncAttributeMaxDynamicSharedMemorySize, SMEM_TOT);
    cudaFuncSetAttribute(k_l2out, cudaFuncAttributeMaxDynamicSharedMemorySize, SMEM_TOT);

    // 0: mean, 1: router, 2: fused conversions (no transpose region)
    k_mean<<<(BB * DD + 255) / 256, 256>>>(x);
    k_router<<<1, 256>>>(router_w, out, bnd, has_aux);
    k_convert<<<NB_TOTAL, 256>>>(x, tok_w1, tok_w2, ch_w1, ch_w2);

    // 3: merged L1 GEMM (writes weight-pre-scaled fp16 hidden)
    dim3 g_l1(192, 1, NPAIR);
    k_l1<<<g_l1, 128, SMEM_TOT>>>(tok_b1, ch_b1);

    // 4: fused L2 + combine (both pairs accumulate, writes out directly)
    dim3 g_l2o(48, 1, BB);
    k_l2out<<<g_l2o, 128, SMEM_TOT>>>(tok_b2, ch_b2, out);
}